// round 13
// baseline (speedup 1.0000x reference)
#include <cuda_runtime.h>
#include <cuda_fp16.h>
#include <math.h>
#include <stdint.h>

#define BB   2
#define SS   2048
#define DD   1024
#define HH   16
#define HD   64
#define DFF  4096
#define WIN  128
#define MTOT (BB * SS)

// ---------------- device scratch ----------------
__device__ float  g_tmp [(size_t)MTOT * DD];
__device__ float  g_x2  [(size_t)MTOT * DD];
__device__ __half g_qkvh[(size_t)MTOT * 3 * DD];
__device__ __half g_x_h [(size_t)MTOT * DD];
__device__ __half g_at_h[(size_t)MTOT * DD];
__device__ __half g_x2_h[(size_t)MTOT * DD];
__device__ __half g_ff_h[(size_t)MTOT * DFF];
__device__ __half g_iw_h[(size_t)3*DD*DD];
__device__ __half g_ow_h[(size_t)DD*DD];
__device__ __half g_w1_h[(size_t)DFF*DD];
__device__ __half g_w2_h[(size_t)DD*DFF];

// ---------------- PTX helpers ----------------
__device__ __forceinline__ uint32_t smem_u32(const void* p) {
    uint32_t a;
    asm("{ .reg .u64 t; cvta.to.shared.u64 t, %1; cvt.u32.u64 %0, t; }" : "=r"(a) : "l"(p));
    return a;
}
__device__ __forceinline__ void cp16(uint32_t dst, const void* src) {
    asm volatile("cp.async.cg.shared.global [%0], [%1], 16;" :: "r"(dst), "l"(src));
}
__device__ __forceinline__ void cp_commit() {
    asm volatile("cp.async.commit_group;" ::: "memory");
}
template<int N>
__device__ __forceinline__ void cp_wait() {
    asm volatile("cp.async.wait_group %0;" :: "n"(N) : "memory");
}
__device__ __forceinline__ void mma_f16(float* c, const uint32_t* a, const uint32_t* b) {
    asm volatile(
        "mma.sync.aligned.m16n8k16.row.col.f32.f16.f16.f32 "
        "{%0,%1,%2,%3}, {%4,%5,%6,%7}, {%8,%9}, {%0,%1,%2,%3};"
        : "+f"(c[0]), "+f"(c[1]), "+f"(c[2]), "+f"(c[3])
        : "r"(a[0]), "r"(a[1]), "r"(a[2]), "r"(a[3]), "r"(b[0]), "r"(b[1]));
}
// fp16-accumulate variant: D,C are 2x .f16x2 regs
__device__ __forceinline__ void mma_f16h(uint32_t* c, const uint32_t* a, const uint32_t* b) {
    asm volatile(
        "mma.sync.aligned.m16n8k16.row.col.f16.f16.f16.f16 "
        "{%0,%1}, {%2,%3,%4,%5}, {%6,%7}, {%0,%1};"
        : "+r"(c[0]), "+r"(c[1])
        : "r"(a[0]), "r"(a[1]), "r"(a[2]), "r"(a[3]), "r"(b[0]), "r"(b[1]));
}
__device__ __forceinline__ void ldsm_x4(uint32_t* r, uint32_t addr) {
    asm volatile("ldmatrix.sync.aligned.m8n8.x4.shared.b16 {%0,%1,%2,%3}, [%4];"
                 : "=r"(r[0]), "=r"(r[1]), "=r"(r[2]), "=r"(r[3]) : "r"(addr));
}
__device__ __forceinline__ void ldsm_x4_t(uint32_t* r, uint32_t addr) {
    asm volatile("ldmatrix.sync.aligned.m8n8.x4.trans.shared.b16 {%0,%1,%2,%3}, [%4];"
                 : "=r"(r[0]), "=r"(r[1]), "=r"(r[2]), "=r"(r[3]) : "r"(addr));
}

// ---------------- shared GEMM geometry ----------------
#define PITCH   72
#define A_MAT   (128 * PITCH)
#define B_MAT   (128 * PITCH)
#define STAGE_E (A_MAT + B_MAT)            // 18432 elems
#define STAGE_B (STAGE_E * 2)              // 36864 bytes
#define GEMM_SMEM (3 * STAGE_B)            // 110592 bytes

// ---------------- fp32-accumulate GEMM (proven R11/R12 kernel) ----------------
template<bool RELU, bool WF32, bool WF16>
__global__ __launch_bounds__(256, 2)
void gemm_f16(const __half* __restrict__ A, const __half* __restrict__ B,
              const float* __restrict__ bias,
              float* __restrict__ C, __half* __restrict__ Ch,
              int M, int N, int K)
{
    extern __shared__ __align__(16) __half sm[];
    const uint32_t sbase = smem_u32(sm);
    const int tid  = threadIdx.x;
    const int warp = tid >> 5, lane = tid & 31;
    const int gid  = lane >> 2, tig = lane & 3;
    const int wm   = warp >> 2, wn = warp & 3;
    const int bx = blockIdx.x, by = blockIdx.y;

    const size_t Abase = (size_t)(by * 128) * K;
    const size_t Bbase = (size_t)(bx * 128) * K;

    auto load_stage = [&](int chunk, int s) {
        const int k0 = chunk * 64;
        const uint32_t sb = sbase + s * STAGE_B;
#pragma unroll
        for (int i = 0; i < 8; i++) {
            int idx = i * 256 + tid;
            if (idx < 1024) {
                int r = idx >> 3, c = idx & 7;
                cp16(sb + (uint32_t)(r * PITCH + c * 8) * 2,
                     A + Abase + (size_t)r * K + k0 + c * 8);
            } else {
                int j = idx - 1024;
                int r = j >> 3, c = j & 7;
                cp16(sb + (uint32_t)(A_MAT + r * PITCH + c * 8) * 2,
                     B + Bbase + (size_t)r * K + k0 + c * 8);
            }
        }
    };

    float acc[4][4][4];
#pragma unroll
    for (int i = 0; i < 4; i++)
#pragma unroll
        for (int j = 0; j < 4; j++)
#pragma unroll
            for (int v = 0; v < 4; v++) acc[i][j][v] = 0.f;

    const uint32_t a_off = (uint32_t)((wm * 64 + (lane & 15)) * PITCH) * 2 + (lane >> 4) * 16;
    const uint32_t b_off4 = (uint32_t)((wn * 32 + ((lane >> 4) & 1) * 8 + (lane & 7)) * PITCH) * 2
                          + ((lane >> 3) & 1) * 16;

    const int nch = K >> 6;
    load_stage(0, 0); cp_commit();
    load_stage(1, 1); cp_commit();

    for (int c = 0; c < nch; c++) {
        cp_wait<1>();
        __syncthreads();
        if (c + 2 < nch) load_stage(c + 2, (c + 2) % 3);
        cp_commit();

        const uint32_t Ahs = sbase + (c % 3) * STAGE_B;
        const uint32_t Bhs = Ahs + A_MAT * 2;

#pragma unroll
        for (int kk = 0; kk < 64; kk += 16) {
            uint32_t bf[4][2];
#pragma unroll
            for (int p = 0; p < 2; p++) {
                uint32_t t4[4];
                ldsm_x4(t4, Bhs + b_off4 + (uint32_t)(p * 16 * PITCH) * 2 + kk * 2);
                bf[2 * p][0]     = t4[0];
                bf[2 * p][1]     = t4[1];
                bf[2 * p + 1][0] = t4[2];
                bf[2 * p + 1][1] = t4[3];
            }
            uint32_t af[2][4];
            ldsm_x4(af[0], Ahs + a_off + kk * 2);
#pragma unroll
            for (int mt = 0; mt < 4; mt++) {
                if (mt < 3)
                    ldsm_x4(af[(mt + 1) & 1],
                            Ahs + a_off + (uint32_t)((mt + 1) * 16 * PITCH) * 2 + kk * 2);
#pragma unroll
                for (int nt = 0; nt < 4; nt++)
                    mma_f16(acc[mt][nt], af[mt & 1], bf[nt]);
            }
        }
    }

#pragma unroll
    for (int mt = 0; mt < 4; mt++) {
#pragma unroll
        for (int nt = 0; nt < 4; nt++) {
            const int col = bx * 128 + wn * 32 + nt * 8 + tig * 2;
            const float2 bv = *(const float2*)&bias[col];
            const int row0 = by * 128 + wm * 64 + mt * 16 + gid;
#pragma unroll
            for (int half = 0; half < 2; half++) {
                const int row = row0 + half * 8;
                float v0 = acc[mt][nt][half * 2]     + bv.x;
                float v1 = acc[mt][nt][half * 2 + 1] + bv.y;
                if (RELU) { v0 = fmaxf(v0, 0.f); v1 = fmaxf(v1, 0.f); }
                const size_t o = (size_t)row * N + col;
                if (WF32) *(float2*)(C + o) = make_float2(v0, v1);
                if (WF16) {
                    __half2 hp;
                    hp.x = __float2half_rn(v0);
                    hp.y = __float2half_rn(v1);
                    *(__half2*)(Ch + o) = hp;
                }
            }
        }
    }
}

// ---------------- fp16-chunk-accumulate GEMM (FFN only) ----------------
// Accumulates each K=64 chunk in fp16 (4 HMMA roundings on small partials),
// promotes to running fp32 once per chunk.  ~160 regs -> 1 CTA/SM.
template<bool RELU, bool WF32, bool WF16>
__global__ __launch_bounds__(256)
void gemm_f16a(const __half* __restrict__ A, const __half* __restrict__ B,
               const float* __restrict__ bias,
               float* __restrict__ C, __half* __restrict__ Ch,
               int M, int N, int K)
{
    extern __shared__ __align__(16) __half sm[];
    const uint32_t sbase = smem_u32(sm);
    const int tid  = threadIdx.x;
    const int warp = tid >> 5, lane = tid & 31;
    const int gid  = lane >> 2, tig = lane & 3;
    const int wm   = warp >> 2, wn = warp & 3;
    const int bx = blockIdx.x, by = blockIdx.y;

    const size_t Abase = (size_t)(by * 128) * K;
    const size_t Bbase = (size_t)(bx * 128) * K;

    auto load_stage = [&](int chunk, int s) {
        const int k0 = chunk * 64;
        const uint32_t sb = sbase + s * STAGE_B;
#pragma unroll
        for (int i = 0; i < 8; i++) {
            int idx = i * 256 + tid;
            if (idx < 1024) {
                int r = idx >> 3, c = idx & 7;
                cp16(sb + (uint32_t)(r * PITCH + c * 8) * 2,
                     A + Abase + (size_t)r * K + k0 + c * 8);
            } else {
                int j = idx - 1024;
                int r = j >> 3, c = j & 7;
                cp16(sb + (uint32_t)(A_MAT + r * PITCH + c * 8) * 2,
                     B + Bbase + (size_t)r * K + k0 + c * 8);
            }
        }
    };

    float acc[4][4][4];
#pragma unroll
    for (int i = 0; i < 4; i++)
#pragma unroll
        for (int j = 0; j < 4; j++)
#pragma unroll
            for (int v = 0; v < 4; v++) acc[i][j][v] = 0.f;

    const uint32_t a_off = (uint32_t)((wm * 64 + (lane & 15)) * PITCH) * 2 + (lane >> 4) * 16;
    const uint32_t b_off4 = (uint32_t)((wn * 32 + ((lane >> 4) & 1) * 8 + (lane & 7)) * PITCH) * 2
                          + ((lane >> 3) & 1) * 16;

    const int nch = K >> 6;
    load_stage(0, 0); cp_commit();
    load_stage(1, 1); cp_commit();

    for (int c = 0; c < nch; c++) {
        cp_wait<1>();
        __syncthreads();
        if (c + 2 < nch) load_stage(c + 2, (c + 2) % 3);
        cp_commit();

        const uint32_t Ahs = sbase + (c % 3) * STAGE_B;
        const uint32_t Bhs = Ahs + A_MAT * 2;

        // per-chunk fp16 accumulators (zeroed each chunk)
        uint32_t h2a[4][4][2];
#pragma unroll
        for (int i = 0; i < 4; i++)
#pragma unroll
            for (int j = 0; j < 4; j++) { h2a[i][j][0] = 0u; h2a[i][j][1] = 0u; }

#pragma unroll
        for (int kk = 0; kk < 64; kk += 16) {
            uint32_t bf[4][2];
#pragma unroll
            for (int p = 0; p < 2; p++) {
                uint32_t t4[4];
                ldsm_x4(t4, Bhs + b_off4 + (uint32_t)(p * 16 * PITCH) * 2 + kk * 2);
                bf[2 * p][0]     = t4[0];
                bf[2 * p][1]     = t4[1];
                bf[2 * p + 1][0] = t4[2];
                bf[2 * p + 1][1] = t4[3];
            }
#pragma unroll
            for (int mt = 0; mt < 4; mt++) {
                uint32_t af[4];
                ldsm_x4(af, Ahs + a_off + (uint32_t)(mt * 16 * PITCH) * 2 + kk * 2);
#pragma unroll
                for (int nt = 0; nt < 4; nt++)
                    mma_f16h(h2a[mt][nt], af, bf[nt]);
            }
        }

        // promote chunk partials to fp32
#pragma unroll
        for (int mt = 0; mt < 4; mt++)
#pragma unroll
            for (int nt = 0; nt < 4; nt++) {
                float2 lo = __half22float2(*(__half2*)&h2a[mt][nt][0]);
                float2 hi = __half22float2(*(__half2*)&h2a[mt][nt][1]);
                acc[mt][nt][0] += lo.x; acc[mt][nt][1] += lo.y;
                acc[mt][nt][2] += hi.x; acc[mt][nt][3] += hi.y;
            }
    }

#pragma unroll
    for (int mt = 0; mt < 4; mt++) {
#pragma unroll
        for (int nt = 0; nt < 4; nt++) {
            const int col = bx * 128 + wn * 32 + nt * 8 + tig * 2;
            const float2 bv = *(const float2*)&bias[col];
            const int row0 = by * 128 + wm * 64 + mt * 16 + gid;
#pragma unroll
            for (int half = 0; half < 2; half++) {
                const int row = row0 + half * 8;
                float v0 = acc[mt][nt][half * 2]     + bv.x;
                float v1 = acc[mt][nt][half * 2 + 1] + bv.y;
                if (RELU) { v0 = fmaxf(v0, 0.f); v1 = fmaxf(v1, 0.f); }
                const size_t o = (size_t)row * N + col;
                if (WF32) *(float2*)(C + o) = make_float2(v0, v1);
                if (WF16) {
                    __half2 hp;
                    hp.x = __float2half_rn(v0);
                    hp.y = __float2half_rn(v1);
                    *(__half2*)(Ch + o) = hp;
                }
            }
        }
    }
}

// ---------------- fused fp32->fp16 conversions (ILP 2, 512 thr) ----------
#define N4_X   1048576
#define N4_IW  786432
#define N4_OW  262144
#define N4_W1  1048576
#define N4_W2  1048576
#define N4_TOT 4194304

__global__ __launch_bounds__(512)
void cvt_all(const float* __restrict__ x,  __half* __restrict__ xh,
             const float* __restrict__ iw, __half* __restrict__ iwh,
             const float* __restrict__ ow, __half* __restrict__ owh,
             const float* __restrict__ w1, __half* __restrict__ w1h,
             const float* __restrict__ w2, __half* __restrict__ w2h)
{
    auto locate = [&](int i, const float*& s, __half*& d, int& j) {
        if      (i < N4_X)                         { s = x;  d = xh;  j = i; }
        else if (i < N4_X + N4_IW)                 { s = iw; d = iwh; j = i - N4_X; }
        else if (i < N4_X + N4_IW + N4_OW)         { s = ow; d = owh; j = i - N4_X - N4_IW; }
        else if (i < N4_X + N4_IW + N4_OW + N4_W1) { s = w1; d = w1h; j = i - N4_X - N4_IW - N4_OW; }
        else                                       { s = w2; d = w2h; j = i - N4_X - N4_IW - N4_OW - N4_W1; }
    };
    const int i0 = blockIdx.x * 1024 + threadIdx.x;
    const int i1 = i0 + 512;

    const float* s0; __half* d0; int j0;
    const float* s1; __half* d1; int j1;
    bool v0 = i0 < N4_TOT, v1 = i1 < N4_TOT;
    float4 a4, b4;
    if (v0) { locate(i0, s0, d0, j0); a4 = ((const float4*)s0)[j0]; }
    if (v1) { locate(i1, s1, d1, j1); b4 = ((const float4*)s1)[j1]; }

    if (v0) {
        __half2 a, b;
        a.x = __float2half_rn(a4.x); a.y = __float2half_rn(a4.y);
        b.x = __float2half_rn(a4.z); b.y = __float2half_rn(a4.w);
        ((__half2*)d0)[j0*2]   = a;
        ((__half2*)d0)[j0*2+1] = b;
    }
    if (v1) {
        __half2 a, b;
        a.x = __float2half_rn(b4.x); a.y = __float2half_rn(b4.y);
        b.x = __float2half_rn(b4.z); b.y = __float2half_rn(b4.w);
        ((__half2*)d1)[j1*2]   = a;
        ((__half2*)d1)[j1*2+1] = b;
    }
}

// ---------------- MMA banded flash attention, 3-stage K/V pipeline ----------
__global__ __launch_bounds__(256)
void attn_mma(const __half* __restrict__ qkvh, __half* __restrict__ outh)
{
    __shared__ __align__(16) __half asmem[(128 + 3 * 64) * 72];
    const uint32_t sQ = smem_u32(asmem);

    const int tid = threadIdx.x, warp = tid >> 5, lane = tid & 31;
    const int gid = lane >> 2, tig = lane & 3;
    const int b = blockIdx.z, h = blockIdx.y, q0 = blockIdx.x * 128;
    const __half* base = qkvh + (size_t)b * SS * (3 * DD);

    const int row0 = q0 + warp * 16 + gid;
    const int row1 = row0 + 8;
    const int klo = max(q0 - WIN, 0);
    const int khi = min(q0 + 127 + WIN, SS - 1);
    const int ntiles = (khi - klo + 32) / 32;

    auto load_kv = [&](int it, int s) {
        const int kt = klo + it * 32;
        const int nk = khi - kt + 1 < 32 ? khi - kt + 1 : 32;
        const uint32_t sK = sQ + (uint32_t)(128 + s * 64) * 72 * 2;
        const uint32_t sV = sK + 32 * 72 * 2;
        __half* pK = asmem + (128 + s * 64) * 72;
        __half* pV = pK + 32 * 72;
        int r = tid >> 3, c = tid & 7;
        size_t grow = (size_t)(kt + r) * (3 * DD) + h * HD + c * 8;
        if (r < nk) cp16(sK + (uint32_t)(r * PITCH + c * 8) * 2, base + grow + DD);
        else        *(uint4*)(pK + r * PITCH + c * 8) = make_uint4(0, 0, 0, 0);
        if (r < nk) cp16(sV + (uint32_t)(r * PITCH + c * 8) * 2, base + grow + 2 * DD);
        else        *(uint4*)(pV + r * PITCH + c * 8) = make_uint4(0, 0, 0, 0);
    };

#pragma unroll
    for (int i = 0; i < 4; i++) {
        int idx = i * 256 + tid;
        int r = idx >> 3, c = idx & 7;
        cp16(sQ + (uint32_t)(r * PITCH + c * 8) * 2,
             base + (size_t)(q0 + r) * (3 * DD) + h * HD + c * 8);
    }
    load_kv(0, 0); cp_commit();
    if (ntiles > 1) load_kv(1, 1);
    cp_commit();

    uint32_t qf[4][4];
    float o[8][4];
#pragma unroll
    for (int i = 0; i < 8; i++)
#pragma unroll
        for (int j = 0; j < 4; j++) o[i][j] = 0.f;
    float m0 = -1e30f, m1 = -1e30f, l0 = 0.f, l1 = 0.f;

    for (int it = 0; it < ntiles; it++) {
        cp_wait<1>();
        __syncthreads();
        if (it + 2 < ntiles) load_kv(it + 2, (it + 2) % 3);
        cp_commit();

        if (it == 0) {
            const uint32_t qa = sQ + (uint32_t)((warp * 16 + (lane & 15)) * PITCH) * 2 + (lane >> 4) * 16;
#pragma unroll
            for (int kc = 0; kc < 4; kc++) ldsm_x4(qf[kc], qa + kc * 32);
        }

        const int kt = klo + it * 32;
        const int s = it % 3;
        const uint32_t sK = sQ + (uint32_t)(128 + s * 64) * 72 * 2;
        const uint32_t sV = sK + 32 * 72 * 2;

        float sc[4][4];
#pragma unroll
        for (int nt = 0; nt < 4; nt++)
#pragma unroll
            for (int j = 0; j < 4; j++) sc[nt][j] = 0.f;
#pragma unroll
        for (int nt = 0; nt < 4; nt++) {
            const uint32_t kbase = sK + (uint32_t)((nt * 8 + (lane & 7)) * PITCH) * 2 + (lane >> 3) * 16;
#pragma unroll
            for (int kp = 0; kp < 2; kp++) {
                uint32_t kf[4];
                ldsm_x4(kf, kbase + kp * 64);
                mma_f16(sc[nt], qf[kp * 2],     &kf[0]);
                mma_f16(sc[nt], qf[kp * 2 + 1], &kf[2]);
            }
        }

        float mx0 = -1e30f, mx1 = -1e30f;
#pragma unroll
        for (int nt = 0; nt < 4; nt++) {
            const int c0 = kt + nt * 8 + tig * 2, c1 = c0 + 1;
            float s2;
            s2 = sc[nt][0] * 0.125f;
            sc[nt][0] = (c0 >= row0 - WIN && c0 <= row0 + WIN && c0 <= khi) ? s2 : -1e30f;
            s2 = sc[nt][1] * 0.125f;
            sc[nt][1] = (c1 >= row0 - WIN && c1 <= row0 + WIN && c1 <= khi) ? s2 : -1e30f;
            s2 = sc[nt][2] * 0.125f;
            sc[nt][2] = (c0 >= row1 - WIN && c0 <= row1 + WIN && c0 <= khi) ? s2 : -1e30f;
            s2 = sc[nt][3] * 0.125f;
            sc[nt][3] = (c1 >= row1 - WIN && c1 <= row1 + WIN && c1 <= khi) ? s2 : -1e30f;
            mx0 = fmaxf(mx0, fmaxf(sc[nt][0], sc[nt][1]));
            mx1 = fmaxf(mx1, fmaxf(sc[nt][2], sc[nt][3]));
        }
        mx0 = fmaxf(mx0, __shfl_xor_sync(0xFFFFFFFFu, mx0, 1));
        mx0 = fmaxf(mx0, __shfl_xor_sync(0xFFFFFFFFu, mx0, 2));
        mx1 = fmaxf(mx1, __shfl_xor_sync(0xFFFFFFFFu, mx1, 1));
        mx1 = fmaxf(mx1, __shfl_xor_sync(0xFFFFFFFFu, mx1, 2));

        const float nm0 = fmaxf(m0, mx0), nm1 = fmaxf(m1, mx1);
        const float e0 = __expf(m0 - nm0), e1 = __expf(m1 - nm1);
        l0 *= e0; l1 *= e1;
#pragma unroll
        for (int ng = 0; ng < 8; ng++) {
            o[ng][0] *= e0; o[ng][1] *= e0;
            o[ng][2] *= e1; o[ng][3] *= e1;
        }
        m0 = nm0; m1 = nm1;

        uint32_t pf[2][4];
#pragma unroll
        for (int nt = 0; nt < 4; nt++) {
            float p0 = __expf(sc[nt][0] - nm0), p1 = __expf(sc[nt][1] - nm0);
            float p2 = __expf(sc[nt][2] - nm1), p3 = __expf(sc[nt][3] - nm1);
            l0 += p0 + p1; l1 += p2 + p3;
            __half2 h01 = __floats2half2_rn(p0, p1);
            __half2 h23 = __floats2half2_rn(p2, p3);
            pf[nt >> 1][(nt & 1) * 2 + 0] = *(uint32_t*)&h01;
            pf[nt >> 1][(nt & 1) * 2 + 1] = *(uint32_t*)&h23;
        }

#pragma unroll
        for (int np = 0; np < 4; np++) {
#pragma unroll
            for (int kc = 0; kc < 2; kc++) {
                uint32_t vf[4];
                ldsm_x4_t(vf, sV + (uint32_t)((kc * 16 + (lane & 15)) * PITCH) * 2 +
                              (np * 2 + (lane >> 4)) * 16);
                mma_f16(o[np * 2],     pf[kc], &vf[0]);
                mma_f16(o[np * 2 + 1], pf[kc], &vf[2]);
            }
        }
    }

    l0 += __shfl_xor_sync(0xFFFFFFFFu, l0, 1);
    l0 += __shfl_xor_sync(0xFFFFFFFFu, l0, 2);
    l1 += __shfl_xor_sync(0xFFFFFFFFu, l1, 1);
    l1 += __shfl_xor_sync(0xFFFFFFFFu, l1, 2);
    const float inv0 = 1.f / l0, inv1 = 1.f / l1;
    __half* o0p = outh + (size_t)(b * SS + row0) * DD + h * HD + tig * 2;
    __half* o1p = outh + (size_t)(b * SS + row1) * DD + h * HD + tig * 2;
#pragma unroll
    for (int ng = 0; ng < 8; ng++) {
        __half2 a = __floats2half2_rn(o[ng][0] * inv0, o[ng][1] * inv0);
        __half2 c = __floats2half2_rn(o[ng][2] * inv1, o[ng][3] * inv1);
        *(__half2*)(o0p + ng * 8) = a;
        *(__half2*)(o1p + ng * 8) = c;
    }
}

// ---------------- fused residual + LayerNorm (+ optional fp16 out) ----------------
__global__ __launch_bounds__(256)
void ln_kernel(const float* __restrict__ A, const float* __restrict__ R,
               const float* __restrict__ g, const float* __restrict__ be,
               float* __restrict__ out, __half* __restrict__ oh)
{
    const int row = blockIdx.x;
    const int t = threadIdx.x;
    const size_t base = (size_t)row * DD;

    float4 av = *(const float4*)(A + base + t * 4);
    float4 rv = *(const float4*)(R + base + t * 4);
    float4 v = make_float4(av.x + rv.x, av.y + rv.y, av.z + rv.z, av.w + rv.w);

    float s = v.x + v.y + v.z + v.w;
    float q = v.x * v.x + v.y * v.y + v.z * v.z + v.w * v.w;
#pragma unroll
    for (int off = 16; off > 0; off >>= 1) {
        s += __shfl_xor_sync(0xFFFFFFFFu, s, off);
        q += __shfl_xor_sync(0xFFFFFFFFu, q, off);
    }
    __shared__ float ss[8], sq[8];
    __shared__ float mu_s, inv_s;
    if ((t & 31) == 0) { ss[t >> 5] = s; sq[t >> 5] = q; }
    __syncthreads();
    if (t == 0) {
        float S = 0.f, Q = 0.f;
#pragma unroll
        for (int i = 0; i < 8; i++) { S += ss[i]; Q += sq[i]; }
        float mu = S * (1.f / DD);
        float var = Q * (1.f / DD) - mu * mu;
        mu_s = mu;
        inv_s = rsqrtf(var + 1e-5f);
    }
    __syncthreads();
    const float mu = mu_s, inv = inv_s;

    float4 gv = *(const float4*)(g + t * 4);
    float4 bv = *(const float4*)(be + t * 4);
    float4 o;
    o.x = (v.x - mu) * inv * gv.x + bv.x;
    o.y = (v.y - mu) * inv * gv.y + bv.y;
    o.z = (v.z - mu) * inv * gv.z + bv.z;
    o.w = (v.w - mu) * inv * gv.w + bv.w;
    *(float4*)(out + base + t * 4) = o;

    if (oh != nullptr) {
        __half2 h0, h1;
        h0.x = __float2half_rn(o.x); h0.y = __float2half_rn(o.y);
        h1.x = __float2half_rn(o.z); h1.y = __float2half_rn(o.w);
        *(__half2*)(oh + base + t * 4)     = h0;
        *(__half2*)(oh + base + t * 4 + 2) = h1;
    }
}

// ---------------- host ----------------
extern "C" void kernel_launch(void* const* d_in, const int* in_sizes, int n_in,
                              void* d_out, int out_size)
{
    (void)in_sizes; (void)n_in; (void)out_size;
    const float* x     = (const float*)d_in[0];
    const float* in_w  = (const float*)d_in[1];
    const float* in_b  = (const float*)d_in[2];
    const float* out_w = (const float*)d_in[3];
    const float* out_b = (const float*)d_in[4];
    const float* ln1g  = (const float*)d_in[5];
    const float* ln1b  = (const float*)d_in[6];
    const float* w1    = (const float*)d_in[7];
    const float* b1    = (const float*)d_in[8];
    const float* w2    = (const float*)d_in[9];
    const float* b2    = (const float*)d_in[10];
    const float* ln2g  = (const float*)d_in[11];
    const float* ln2b  = (const float*)d_in[12];
    float* out = (float*)d_out;

    float *tmp, *x2;
    __half *qkvh, *xh, *ath, *x2h, *ffh, *iwh, *owh, *w1h, *w2h;
    cudaGetSymbolAddress((void**)&tmp,  g_tmp);
    cudaGetSymbolAddress((void**)&x2,   g_x2);
    cudaGetSymbolAddress((void**)&qkvh, g_qkvh);
    cudaGetSymbolAddress((void**)&xh,   g_x_h);
    cudaGetSymbolAddress((void**)&ath,  g_at_h);
    cudaGetSymbolAddress((void**)&x2h,  g_x2_h);
    cudaGetSymbolAddress((void**)&ffh,  g_ff_h);
    cudaGetSymbolAddress((void**)&iwh,  g_iw_h);
    cudaGetSymbolAddress((void**)&owh,  g_ow_h);
    cudaGetSymbolAddress((void**)&w1h,  g_w1_h);
    cudaGetSymbolAddress((void**)&w2h,  g_w2_h);

    cudaFuncSetAttribute(gemm_f16<false, true, false>,
                         cudaFuncAttributeMaxDynamicSharedMemorySize, GEMM_SMEM);
    cudaFuncSetAttribute(gemm_f16<false, false, true>,
                         cudaFuncAttributeMaxDynamicSharedMemorySize, GEMM_SMEM);
    cudaFuncSetAttribute(gemm_f16a<true, false, true>,
                         cudaFuncAttributeMaxDynamicSharedMemorySize, GEMM_SMEM);
    cudaFuncSetAttribute(gemm_f16a<false, true, false>,
                         cudaFuncAttributeMaxDynamicSharedMemorySize, GEMM_SMEM);

    cvt_all<<<(N4_TOT + 1023) / 1024, 512>>>(x, xh, in_w, iwh, out_w, owh, w1, w1h, w2, w2h);

    // 1. QKV projection -> fp16 qkv  (fp32 accum, proven)
    gemm_f16<false, false, true><<<dim3(3 * DD / 128, MTOT / 128), 256, GEMM_SMEM>>>(
        xh, iwh, in_b, nullptr, qkvh, MTOT, 3 * DD, DD);
    // 2. MMA attention -> fp16
    attn_mma<<<dim3(SS / 128, HH, BB), 256>>>(qkvh, ath);
    // 3. out_proj -> fp32  (fp32 accum, proven)
    gemm_f16<false, true, false><<<dim3(DD / 128, MTOT / 128), 256, GEMM_SMEM>>>(
        ath, owh, out_b, tmp, nullptr, MTOT, DD, DD);
    // 4. ln1 -> fp32 + fp16
    ln_kernel<<<MTOT, 256>>>(x, tmp, ln1g, ln1b, x2, x2h);
    // 5. ffn1 (relu) -> fp16  (fp16 chunk accum)
    gemm_f16a<true, false, true><<<dim3(DFF / 128, MTOT / 128), 256, GEMM_SMEM>>>(
        x2h, w1h, b1, nullptr, ffh, MTOT, DFF, DD);
    // 6. ffn2 -> fp32  (fp16 chunk accum)
    gemm_f16a<false, true, false><<<dim3(DD / 128, MTOT / 128), 256, GEMM_SMEM>>>(
        ffh, w2h, b2, tmp, nullptr, MTOT, DD, DFF);
    // 7. ln2 -> final out
    ln_kernel<<<MTOT, 256>>>(x2, tmp, ln2g, ln2b, out, nullptr);
}

// round 14
// speedup vs baseline: 1.1357x; 1.1357x over previous
#include <cuda_runtime.h>
#include <cuda_fp16.h>
#include <math.h>
#include <stdint.h>

#define BB   2
#define SS   2048
#define DD   1024
#define HH   16
#define HD   64
#define DFF  4096
#define WIN  128
#define MTOT (BB * SS)

// ---------------- device scratch ----------------
__device__ float  g_tmp [(size_t)MTOT * DD];
__device__ float  g_x2  [(size_t)MTOT * DD];
__device__ __half g_qkvh[(size_t)MTOT * 3 * DD];
__device__ __half g_x_h [(size_t)MTOT * DD];
__device__ __half g_at_h[(size_t)MTOT * DD];
__device__ __half g_x2_h[(size_t)MTOT * DD];
__device__ __half g_ff_h[(size_t)MTOT * DFF];
__device__ __half g_iw_h[(size_t)3*DD*DD];
__device__ __half g_ow_h[(size_t)DD*DD];
__device__ __half g_w1_h[(size_t)DFF*DD];
__device__ __half g_w2_h[(size_t)DD*DFF];

// ---------------- PTX helpers ----------------
__device__ __forceinline__ uint32_t smem_u32(const void* p) {
    uint32_t a;
    asm("{ .reg .u64 t; cvta.to.shared.u64 t, %1; cvt.u32.u64 %0, t; }" : "=r"(a) : "l"(p));
    return a;
}
__device__ __forceinline__ void cp16(uint32_t dst, const void* src) {
    asm volatile("cp.async.cg.shared.global [%0], [%1], 16;" :: "r"(dst), "l"(src));
}
__device__ __forceinline__ void cp_commit() {
    asm volatile("cp.async.commit_group;" ::: "memory");
}
template<int N>
__device__ __forceinline__ void cp_wait() {
    asm volatile("cp.async.wait_group %0;" :: "n"(N) : "memory");
}
__device__ __forceinline__ void mma_f16(float* c, const uint32_t* a, const uint32_t* b) {
    asm volatile(
        "mma.sync.aligned.m16n8k16.row.col.f32.f16.f16.f32 "
        "{%0,%1,%2,%3}, {%4,%5,%6,%7}, {%8,%9}, {%0,%1,%2,%3};"
        : "+f"(c[0]), "+f"(c[1]), "+f"(c[2]), "+f"(c[3])
        : "r"(a[0]), "r"(a[1]), "r"(a[2]), "r"(a[3]), "r"(b[0]), "r"(b[1]));
}
__device__ __forceinline__ void ldsm_x4(uint32_t* r, uint32_t addr) {
    asm volatile("ldmatrix.sync.aligned.m8n8.x4.shared.b16 {%0,%1,%2,%3}, [%4];"
                 : "=r"(r[0]), "=r"(r[1]), "=r"(r[2]), "=r"(r[3]) : "r"(addr));
}
__device__ __forceinline__ void ldsm_x4_t(uint32_t* r, uint32_t addr) {
    asm volatile("ldmatrix.sync.aligned.m8n8.x4.trans.shared.b16 {%0,%1,%2,%3}, [%4];"
                 : "=r"(r[0]), "=r"(r[1]), "=r"(r[2]), "=r"(r[3]) : "r"(addr));
}

// ---------------- fp32-accumulate GEMM (R12 kernel, AT the mma.sync floor) ----
#define PITCH   72
#define A_MAT   (128 * PITCH)
#define B_MAT   (128 * PITCH)
#define STAGE_E (A_MAT + B_MAT)            // 18432 elems
#define STAGE_B (STAGE_E * 2)              // 36864 bytes
#define GEMM_SMEM (3 * STAGE_B)            // 110592 bytes

template<bool RELU, bool WF32, bool WF16>
__global__ __launch_bounds__(256, 2)
void gemm_f16(const __half* __restrict__ A, const __half* __restrict__ B,
              const float* __restrict__ bias,
              float* __restrict__ C, __half* __restrict__ Ch,
              int M, int N, int K)
{
    extern __shared__ __align__(16) __half sm[];
    const uint32_t sbase = smem_u32(sm);
    const int tid  = threadIdx.x;
    const int warp = tid >> 5, lane = tid & 31;
    const int gid  = lane >> 2, tig = lane & 3;
    const int wm   = warp >> 2, wn = warp & 3;
    const int bx = blockIdx.x, by = blockIdx.y;

    const size_t Abase = (size_t)(by * 128) * K;
    const size_t Bbase = (size_t)(bx * 128) * K;

    auto load_stage = [&](int chunk, int s) {
        const int k0 = chunk * 64;
        const uint32_t sb = sbase + s * STAGE_B;
#pragma unroll
        for (int i = 0; i < 8; i++) {
            int idx = i * 256 + tid;
            if (idx < 1024) {
                int r = idx >> 3, c = idx & 7;
                cp16(sb + (uint32_t)(r * PITCH + c * 8) * 2,
                     A + Abase + (size_t)r * K + k0 + c * 8);
            } else {
                int j = idx - 1024;
                int r = j >> 3, c = j & 7;
                cp16(sb + (uint32_t)(A_MAT + r * PITCH + c * 8) * 2,
                     B + Bbase + (size_t)r * K + k0 + c * 8);
            }
        }
    };

    float acc[4][4][4];
#pragma unroll
    for (int i = 0; i < 4; i++)
#pragma unroll
        for (int j = 0; j < 4; j++)
#pragma unroll
            for (int v = 0; v < 4; v++) acc[i][j][v] = 0.f;

    const uint32_t a_off = (uint32_t)((wm * 64 + (lane & 15)) * PITCH) * 2 + (lane >> 4) * 16;
    const uint32_t b_off4 = (uint32_t)((wn * 32 + ((lane >> 4) & 1) * 8 + (lane & 7)) * PITCH) * 2
                          + ((lane >> 3) & 1) * 16;

    const int nch = K >> 6;
    load_stage(0, 0); cp_commit();
    load_stage(1, 1); cp_commit();

    for (int c = 0; c < nch; c++) {
        cp_wait<1>();
        __syncthreads();
        if (c + 2 < nch) load_stage(c + 2, (c + 2) % 3);
        cp_commit();

        const uint32_t Ahs = sbase + (c % 3) * STAGE_B;
        const uint32_t Bhs = Ahs + A_MAT * 2;

#pragma unroll
        for (int kk = 0; kk < 64; kk += 16) {
            uint32_t bf[4][2];
#pragma unroll
            for (int p = 0; p < 2; p++) {
                uint32_t t4[4];
                ldsm_x4(t4, Bhs + b_off4 + (uint32_t)(p * 16 * PITCH) * 2 + kk * 2);
                bf[2 * p][0]     = t4[0];
                bf[2 * p][1]     = t4[1];
                bf[2 * p + 1][0] = t4[2];
                bf[2 * p + 1][1] = t4[3];
            }
            uint32_t af[2][4];
            ldsm_x4(af[0], Ahs + a_off + kk * 2);
#pragma unroll
            for (int mt = 0; mt < 4; mt++) {
                if (mt < 3)
                    ldsm_x4(af[(mt + 1) & 1],
                            Ahs + a_off + (uint32_t)((mt + 1) * 16 * PITCH) * 2 + kk * 2);
#pragma unroll
                for (int nt = 0; nt < 4; nt++)
                    mma_f16(acc[mt][nt], af[mt & 1], bf[nt]);
            }
        }
    }

#pragma unroll
    for (int mt = 0; mt < 4; mt++) {
#pragma unroll
        for (int nt = 0; nt < 4; nt++) {
            const int col = bx * 128 + wn * 32 + nt * 8 + tig * 2;
            const float2 bv = *(const float2*)&bias[col];
            const int row0 = by * 128 + wm * 64 + mt * 16 + gid;
#pragma unroll
            for (int half = 0; half < 2; half++) {
                const int row = row0 + half * 8;
                float v0 = acc[mt][nt][half * 2]     + bv.x;
                float v1 = acc[mt][nt][half * 2 + 1] + bv.y;
                if (RELU) { v0 = fmaxf(v0, 0.f); v1 = fmaxf(v1, 0.f); }
                const size_t o = (size_t)row * N + col;
                if (WF32) *(float2*)(C + o) = make_float2(v0, v1);
                if (WF16) {
                    __half2 hp;
                    hp.x = __float2half_rn(v0);
                    hp.y = __float2half_rn(v1);
                    *(__half2*)(Ch + o) = hp;
                }
            }
        }
    }
}

// ---------------- fused fp32->fp16 conversions (ILP 2, 512 thr) ----------
#define N4_X   1048576
#define N4_IW  786432
#define N4_OW  262144
#define N4_W1  1048576
#define N4_W2  1048576
#define N4_TOT 4194304

__global__ __launch_bounds__(512)
void cvt_all(const float* __restrict__ x,  __half* __restrict__ xh,
             const float* __restrict__ iw, __half* __restrict__ iwh,
             const float* __restrict__ ow, __half* __restrict__ owh,
             const float* __restrict__ w1, __half* __restrict__ w1h,
             const float* __restrict__ w2, __half* __restrict__ w2h)
{
    auto locate = [&](int i, const float*& s, __half*& d, int& j) {
        if      (i < N4_X)                         { s = x;  d = xh;  j = i; }
        else if (i < N4_X + N4_IW)                 { s = iw; d = iwh; j = i - N4_X; }
        else if (i < N4_X + N4_IW + N4_OW)         { s = ow; d = owh; j = i - N4_X - N4_IW; }
        else if (i < N4_X + N4_IW + N4_OW + N4_W1) { s = w1; d = w1h; j = i - N4_X - N4_IW - N4_OW; }
        else                                       { s = w2; d = w2h; j = i - N4_X - N4_IW - N4_OW - N4_W1; }
    };
    const int i0 = blockIdx.x * 1024 + threadIdx.x;
    const int i1 = i0 + 512;

    const float* s0; __half* d0; int j0;
    const float* s1; __half* d1; int j1;
    bool v0 = i0 < N4_TOT, v1 = i1 < N4_TOT;
    float4 a4, b4;
    if (v0) { locate(i0, s0, d0, j0); a4 = ((const float4*)s0)[j0]; }
    if (v1) { locate(i1, s1, d1, j1); b4 = ((const float4*)s1)[j1]; }

    if (v0) {
        __half2 a, b;
        a.x = __float2half_rn(a4.x); a.y = __float2half_rn(a4.y);
        b.x = __float2half_rn(a4.z); b.y = __float2half_rn(a4.w);
        ((__half2*)d0)[j0*2]   = a;
        ((__half2*)d0)[j0*2+1] = b;
    }
    if (v1) {
        __half2 a, b;
        a.x = __float2half_rn(b4.x); a.y = __float2half_rn(b4.y);
        b.x = __float2half_rn(b4.z); b.y = __float2half_rn(b4.w);
        ((__half2*)d1)[j1*2]   = a;
        ((__half2*)d1)[j1*2+1] = b;
    }
}

// ---------------- MMA banded flash attention, 64-key stages, 3-stage pipe ----
// Block: 128 queries x 1 head x 1 batch; 8 warps, 16 q/warp.
// Dynamic smem: Q 128 rows | 3 stages x (K 64 + V 64) rows, pitch 72 halves.
// Spans are always 256 or 384 keys -> exact multiples of 64, no tails.
#define ATTN_SMEM ((128 + 3 * 128) * PITCH * 2)   // 73728 bytes

__global__ __launch_bounds__(256)
void attn_mma(const __half* __restrict__ qkvh, __half* __restrict__ outh)
{
    extern __shared__ __align__(16) __half asm_dyn[];
    const uint32_t sQ = smem_u32(asm_dyn);

    const int tid = threadIdx.x, warp = tid >> 5, lane = tid & 31;
    const int gid = lane >> 2, tig = lane & 3;
    const int b = blockIdx.z, h = blockIdx.y, q0 = blockIdx.x * 128;
    const __half* base = qkvh + (size_t)b * SS * (3 * DD);

    const int row0 = q0 + warp * 16 + gid;
    const int row1 = row0 + 8;
    const int klo = max(q0 - WIN, 0);
    const int khi = min(q0 + 127 + WIN, SS - 1);
    const int ntiles = (khi - klo + 1) >> 6;      // span divisible by 64

    // stage s rows: K at 128 + s*128, V at 128 + s*128 + 64
    auto load_kv = [&](int it, int s) {
        const int kt = klo + it * 64;
        const uint32_t sK = sQ + (uint32_t)(128 + s * 128) * PITCH * 2;
        const uint32_t sV = sK + (uint32_t)64 * PITCH * 2;
#pragma unroll
        for (int i = 0; i < 4; i++) {
            int idx = i * 256 + tid;
            int r = (idx & 511) >> 3, c = idx & 7;
            size_t grow = (size_t)(kt + r) * (3 * DD) + h * HD + c * 8;
            if (idx < 512)
                cp16(sK + (uint32_t)(r * PITCH + c * 8) * 2, base + grow + DD);
            else
                cp16(sV + (uint32_t)(r * PITCH + c * 8) * 2, base + grow + 2 * DD);
        }
    };

    // prologue: Q + KV(0) group 0, KV(1) group 1
#pragma unroll
    for (int i = 0; i < 4; i++) {
        int idx = i * 256 + tid;
        int r = idx >> 3, c = idx & 7;
        cp16(sQ + (uint32_t)(r * PITCH + c * 8) * 2,
             base + (size_t)(q0 + r) * (3 * DD) + h * HD + c * 8);
    }
    load_kv(0, 0); cp_commit();
    if (ntiles > 1) load_kv(1, 1);
    cp_commit();

    uint32_t qf[4][4];
    float o[8][4];
#pragma unroll
    for (int i = 0; i < 8; i++)
#pragma unroll
        for (int j = 0; j < 4; j++) o[i][j] = 0.f;
    float m0 = -1e30f, m1 = -1e30f, l0 = 0.f, l1 = 0.f;

    for (int it = 0; it < ntiles; it++) {
        cp_wait<1>();
        __syncthreads();
        if (it + 2 < ntiles) load_kv(it + 2, (it + 2) % 3);
        cp_commit();

        if (it == 0) {
            const uint32_t qa = sQ + (uint32_t)((warp * 16 + (lane & 15)) * PITCH) * 2 + (lane >> 4) * 16;
#pragma unroll
            for (int kc = 0; kc < 4; kc++) ldsm_x4(qf[kc], qa + kc * 32);
        }

        const int s = it % 3;
        const uint32_t sKst = sQ + (uint32_t)(128 + s * 128) * PITCH * 2;
        const uint32_t sVst = sKst + (uint32_t)64 * PITCH * 2;

        // two 32-key halves per stage (code identical to 32-key tiles)
#pragma unroll
        for (int half32 = 0; half32 < 2; half32++) {
            const int kt = klo + it * 64 + half32 * 32;
            const uint32_t sK = sKst + (uint32_t)(half32 * 32 * PITCH) * 2;
            const uint32_t sV = sVst + (uint32_t)(half32 * 32 * PITCH) * 2;

            float sc[4][4];
#pragma unroll
            for (int nt = 0; nt < 4; nt++)
#pragma unroll
                for (int j = 0; j < 4; j++) sc[nt][j] = 0.f;
#pragma unroll
            for (int nt = 0; nt < 4; nt++) {
                const uint32_t kbase = sK + (uint32_t)((nt * 8 + (lane & 7)) * PITCH) * 2 + (lane >> 3) * 16;
#pragma unroll
                for (int kp = 0; kp < 2; kp++) {
                    uint32_t kf[4];
                    ldsm_x4(kf, kbase + kp * 64);
                    mma_f16(sc[nt], qf[kp * 2],     &kf[0]);
                    mma_f16(sc[nt], qf[kp * 2 + 1], &kf[2]);
                }
            }

            float mx0 = -1e30f, mx1 = -1e30f;
#pragma unroll
            for (int nt = 0; nt < 4; nt++) {
                const int c0 = kt + nt * 8 + tig * 2, c1 = c0 + 1;
                float s2;
                s2 = sc[nt][0] * 0.125f;
                sc[nt][0] = (c0 >= row0 - WIN && c0 <= row0 + WIN && c0 <= khi) ? s2 : -1e30f;
                s2 = sc[nt][1] * 0.125f;
                sc[nt][1] = (c1 >= row0 - WIN && c1 <= row0 + WIN && c1 <= khi) ? s2 : -1e30f;
                s2 = sc[nt][2] * 0.125f;
                sc[nt][2] = (c0 >= row1 - WIN && c0 <= row1 + WIN && c0 <= khi) ? s2 : -1e30f;
                s2 = sc[nt][3] * 0.125f;
                sc[nt][3] = (c1 >= row1 - WIN && c1 <= row1 + WIN && c1 <= khi) ? s2 : -1e30f;
                mx0 = fmaxf(mx0, fmaxf(sc[nt][0], sc[nt][1]));
                mx1 = fmaxf(mx1, fmaxf(sc[nt][2], sc[nt][3]));
            }
            mx0 = fmaxf(mx0, __shfl_xor_sync(0xFFFFFFFFu, mx0, 1));
            mx0 = fmaxf(mx0, __shfl_xor_sync(0xFFFFFFFFu, mx0, 2));
            mx1 = fmaxf(mx1, __shfl_xor_sync(0xFFFFFFFFu, mx1, 1));
            mx1 = fmaxf(mx1, __shfl_xor_sync(0xFFFFFFFFu, mx1, 2));

            const float nm0 = fmaxf(m0, mx0), nm1 = fmaxf(m1, mx1);
            const float e0 = __expf(m0 - nm0), e1 = __expf(m1 - nm1);
            l0 *= e0; l1 *= e1;
#pragma unroll
            for (int ng = 0; ng < 8; ng++) {
                o[ng][0] *= e0; o[ng][1] *= e0;
                o[ng][2] *= e1; o[ng][3] *= e1;
            }
            m0 = nm0; m1 = nm1;

            uint32_t pf[2][4];
#pragma unroll
            for (int nt = 0; nt < 4; nt++) {
                float p0 = __expf(sc[nt][0] - nm0), p1 = __expf(sc[nt][1] - nm0);
                float p2 = __expf(sc[nt][2] - nm1), p3 = __expf(sc[nt][3] - nm1);
                l0 += p0 + p1; l1 += p2 + p3;
                __half2 h01 = __floats2half2_rn(p0, p1);
                __half2 h23 = __floats2half2_rn(p2, p3);
                pf[nt >> 1][(nt & 1) * 2 + 0] = *(uint32_t*)&h01;
                pf[nt >> 1][(nt & 1) * 2 + 1] = *(uint32_t*)&h23;
            }

#pragma unroll
            for (int np = 0; np < 4; np++) {
#pragma unroll
                for (int kc = 0; kc < 2; kc++) {
                    uint32_t vf[4];
                    ldsm_x4_t(vf, sV + (uint32_t)((kc * 16 + (lane & 15)) * PITCH) * 2 +
                                  (np * 2 + (lane >> 4)) * 16);
                    mma_f16(o[np * 2],     pf[kc], &vf[0]);
                    mma_f16(o[np * 2 + 1], pf[kc], &vf[2]);
                }
            }
        }
    }

    l0 += __shfl_xor_sync(0xFFFFFFFFu, l0, 1);
    l0 += __shfl_xor_sync(0xFFFFFFFFu, l0, 2);
    l1 += __shfl_xor_sync(0xFFFFFFFFu, l1, 1);
    l1 += __shfl_xor_sync(0xFFFFFFFFu, l1, 2);
    const float inv0 = 1.f / l0, inv1 = 1.f / l1;
    __half* o0p = outh + (size_t)(b * SS + row0) * DD + h * HD + tig * 2;
    __half* o1p = outh + (size_t)(b * SS + row1) * DD + h * HD + tig * 2;
#pragma unroll
    for (int ng = 0; ng < 8; ng++) {
        __half2 a = __floats2half2_rn(o[ng][0] * inv0, o[ng][1] * inv0);
        __half2 c = __floats2half2_rn(o[ng][2] * inv1, o[ng][3] * inv1);
        *(__half2*)(o0p + ng * 8) = a;
        *(__half2*)(o1p + ng * 8) = c;
    }
}

// ---------------- fused residual + LayerNorm (+ optional fp16 out) ----------------
__global__ __launch_bounds__(256)
void ln_kernel(const float* __restrict__ A, const float* __restrict__ R,
               const float* __restrict__ g, const float* __restrict__ be,
               float* __restrict__ out, __half* __restrict__ oh)
{
    const int row = blockIdx.x;
    const int t = threadIdx.x;
    const size_t base = (size_t)row * DD;

    float4 av = *(const float4*)(A + base + t * 4);
    float4 rv = *(const float4*)(R + base + t * 4);
    float4 v = make_float4(av.x + rv.x, av.y + rv.y, av.z + rv.z, av.w + rv.w);

    float s = v.x + v.y + v.z + v.w;
    float q = v.x * v.x + v.y * v.y + v.z * v.z + v.w * v.w;
#pragma unroll
    for (int off = 16; off > 0; off >>= 1) {
        s += __shfl_xor_sync(0xFFFFFFFFu, s, off);
        q += __shfl_xor_sync(0xFFFFFFFFu, q, off);
    }
    __shared__ float ss[8], sq[8];
    __shared__ float mu_s, inv_s;
    if ((t & 31) == 0) { ss[t >> 5] = s; sq[t >> 5] = q; }
    __syncthreads();
    if (t == 0) {
        float S = 0.f, Q = 0.f;
#pragma unroll
        for (int i = 0; i < 8; i++) { S += ss[i]; Q += sq[i]; }
        float mu = S * (1.f / DD);
        float var = Q * (1.f / DD) - mu * mu;
        mu_s = mu;
        inv_s = rsqrtf(var + 1e-5f);
    }
    __syncthreads();
    const float mu = mu_s, inv = inv_s;

    float4 gv = *(const float4*)(g + t * 4);
    float4 bv = *(const float4*)(be + t * 4);
    float4 o;
    o.x = (v.x - mu) * inv * gv.x + bv.x;
    o.y = (v.y - mu) * inv * gv.y + bv.y;
    o.z = (v.z - mu) * inv * gv.z + bv.z;
    o.w = (v.w - mu) * inv * gv.w + bv.w;
    *(float4*)(out + base + t * 4) = o;

    if (oh != nullptr) {
        __half2 h0, h1;
        h0.x = __float2half_rn(o.x); h0.y = __float2half_rn(o.y);
        h1.x = __float2half_rn(o.z); h1.y = __float2half_rn(o.w);
        *(__half2*)(oh + base + t * 4)     = h0;
        *(__half2*)(oh + base + t * 4 + 2) = h1;
    }
}

// ---------------- host ----------------
extern "C" void kernel_launch(void* const* d_in, const int* in_sizes, int n_in,
                              void* d_out, int out_size)
{
    (void)in_sizes; (void)n_in; (void)out_size;
    const float* x     = (const float*)d_in[0];
    const float* in_w  = (const float*)d_in[1];
    const float* in_b  = (const float*)d_in[2];
    const float* out_w = (const float*)d_in[3];
    const float* out_b = (const float*)d_in[4];
    const float* ln1g  = (const float*)d_in[5];
    const float* ln1b  = (const float*)d_in[6];
    const float* w1    = (const float*)d_in[7];
    const float* b1    = (const float*)d_in[8];
    const float* w2    = (const float*)d_in[9];
    const float* b2    = (const float*)d_in[10];
    const float* ln2g  = (const float*)d_in[11];
    const float* ln2b  = (const float*)d_in[12];
    float* out = (float*)d_out;

    float *tmp, *x2;
    __half *qkvh, *xh, *ath, *x2h, *ffh, *iwh, *owh, *w1h, *w2h;
    cudaGetSymbolAddress((void**)&tmp,  g_tmp);
    cudaGetSymbolAddress((void**)&x2,   g_x2);
    cudaGetSymbolAddress((void**)&qkvh, g_qkvh);
    cudaGetSymbolAddress((void**)&xh,   g_x_h);
    cudaGetSymbolAddress((void**)&ath,  g_at_h);
    cudaGetSymbolAddress((void**)&x2h,  g_x2_h);
    cudaGetSymbolAddress((void**)&ffh,  g_ff_h);
    cudaGetSymbolAddress((void**)&iwh,  g_iw_h);
    cudaGetSymbolAddress((void**)&owh,  g_ow_h);
    cudaGetSymbolAddress((void**)&w1h,  g_w1_h);
    cudaGetSymbolAddress((void**)&w2h,  g_w2_h);

    cudaFuncSetAttribute(gemm_f16<false, true, false>,
                         cudaFuncAttributeMaxDynamicSharedMemorySize, GEMM_SMEM);
    cudaFuncSetAttribute(gemm_f16<false, false, true>,
                         cudaFuncAttributeMaxDynamicSharedMemorySize, GEMM_SMEM);
    cudaFuncSetAttribute(gemm_f16<true, false, true>,
                         cudaFuncAttributeMaxDynamicSharedMemorySize, GEMM_SMEM);
    cudaFuncSetAttribute(attn_mma,
                         cudaFuncAttributeMaxDynamicSharedMemorySize, ATTN_SMEM);

    cvt_all<<<(N4_TOT + 1023) / 1024, 512>>>(x, xh, in_w, iwh, out_w, owh, w1, w1h, w2, w2h);

    // 1. QKV projection -> fp16 qkv
    gemm_f16<false, false, true><<<dim3(3 * DD / 128, MTOT / 128), 256, GEMM_SMEM>>>(
        xh, iwh, in_b, nullptr, qkvh, MTOT, 3 * DD, DD);
    // 2. MMA attention -> fp16 (64-key stages)
    attn_mma<<<dim3(SS / 128, HH, BB), 256, ATTN_SMEM>>>(qkvh, ath);
    // 3. out_proj -> fp32
    gemm_f16<false, true, false><<<dim3(DD / 128, MTOT / 128), 256, GEMM_SMEM>>>(
        ath, owh, out_b, tmp, nullptr, MTOT, DD, DD);
    // 4. ln1 -> fp32 + fp16
    ln_kernel<<<MTOT, 256>>>(x, tmp, ln1g, ln1b, x2, x2h);
    // 5. ffn1 (relu) -> fp16
    gemm_f16<true, false, true><<<dim3(DFF / 128, MTOT / 128), 256, GEMM_SMEM>>>(
        x2h, w1h, b1, nullptr, ffh, MTOT, DFF, DD);
    // 6. ffn2 -> fp32
    gemm_f16<false, true, false><<<dim3(DD / 128, MTOT / 128), 256, GEMM_SMEM>>>(
        ffh, w2h, b2, tmp, nullptr, MTOT, DD, DFF);
    // 7. ln2 -> final out
    ln_kernel<<<MTOT, 256>>>(x2, tmp, ln2g, ln2b, out, nullptr);
}

// round 15
// speedup vs baseline: 1.1403x; 1.0041x over previous
#include <cuda_runtime.h>
#include <cuda_fp16.h>
#include <math.h>
#include <stdint.h>

#define BB   2
#define SS   2048
#define DD   1024
#define HH   16
#define HD   64
#define DFF  4096
#define WIN  128
#define MTOT (BB * SS)

// ---------------- device scratch ----------------
__device__ __half g_tmph[(size_t)MTOT * DD];     // out_proj / ffn2 out (fp16)
__device__ float  g_x2  [(size_t)MTOT * DD];
__device__ __half g_qkvh[(size_t)MTOT * 3 * DD];
__device__ __half g_x_h [(size_t)MTOT * DD];
__device__ __half g_at_h[(size_t)MTOT * DD];
__device__ __half g_x2_h[(size_t)MTOT * DD];
__device__ __half g_ff_h[(size_t)MTOT * DFF];
__device__ __half g_iw_h[(size_t)3*DD*DD];
__device__ __half g_ow_h[(size_t)DD*DD];
__device__ __half g_w1_h[(size_t)DFF*DD];
__device__ __half g_w2_h[(size_t)DD*DFF];

// ---------------- PTX helpers ----------------
__device__ __forceinline__ uint32_t smem_u32(const void* p) {
    uint32_t a;
    asm("{ .reg .u64 t; cvta.to.shared.u64 t, %1; cvt.u32.u64 %0, t; }" : "=r"(a) : "l"(p));
    return a;
}
__device__ __forceinline__ void cp16(uint32_t dst, const void* src) {
    asm volatile("cp.async.cg.shared.global [%0], [%1], 16;" :: "r"(dst), "l"(src));
}
__device__ __forceinline__ void cp_commit() {
    asm volatile("cp.async.commit_group;" ::: "memory");
}
template<int N>
__device__ __forceinline__ void cp_wait() {
    asm volatile("cp.async.wait_group %0;" :: "n"(N) : "memory");
}
__device__ __forceinline__ void mma_f16(float* c, const uint32_t* a, const uint32_t* b) {
    asm volatile(
        "mma.sync.aligned.m16n8k16.row.col.f32.f16.f16.f32 "
        "{%0,%1,%2,%3}, {%4,%5,%6,%7}, {%8,%9}, {%0,%1,%2,%3};"
        : "+f"(c[0]), "+f"(c[1]), "+f"(c[2]), "+f"(c[3])
        : "r"(a[0]), "r"(a[1]), "r"(a[2]), "r"(a[3]), "r"(b[0]), "r"(b[1]));
}
__device__ __forceinline__ void ldsm_x4(uint32_t* r, uint32_t addr) {
    asm volatile("ldmatrix.sync.aligned.m8n8.x4.shared.b16 {%0,%1,%2,%3}, [%4];"
                 : "=r"(r[0]), "=r"(r[1]), "=r"(r[2]), "=r"(r[3]) : "r"(addr));
}
__device__ __forceinline__ void ldsm_x4_t(uint32_t* r, uint32_t addr) {
    asm volatile("ldmatrix.sync.aligned.m8n8.x4.trans.shared.b16 {%0,%1,%2,%3}, [%4];"
                 : "=r"(r[0]), "=r"(r[1]), "=r"(r[2]), "=r"(r[3]) : "r"(addr));
}

// ---------------- fp32-accumulate GEMM (at the mma.sync floor) ----------------
#define PITCH   72
#define A_MAT   (128 * PITCH)
#define B_MAT   (128 * PITCH)
#define STAGE_E (A_MAT + B_MAT)
#define STAGE_B (STAGE_E * 2)
#define GEMM_SMEM (3 * STAGE_B)

template<bool RELU, bool WF16ONLY>
__global__ __launch_bounds__(256, 2)
void gemm_f16(const __half* __restrict__ A, const __half* __restrict__ B,
              const float* __restrict__ bias, __half* __restrict__ Ch,
              int M, int N, int K)
{
    extern __shared__ __align__(16) __half sm[];
    const uint32_t sbase = smem_u32(sm);
    const int tid  = threadIdx.x;
    const int warp = tid >> 5, lane = tid & 31;
    const int gid  = lane >> 2, tig = lane & 3;
    const int wm   = warp >> 2, wn = warp & 3;
    const int bx = blockIdx.x, by = blockIdx.y;

    const size_t Abase = (size_t)(by * 128) * K;
    const size_t Bbase = (size_t)(bx * 128) * K;

    auto load_stage = [&](int chunk, int s) {
        const int k0 = chunk * 64;
        const uint32_t sb = sbase + s * STAGE_B;
#pragma unroll
        for (int i = 0; i < 8; i++) {
            int idx = i * 256 + tid;
            if (idx < 1024) {
                int r = idx >> 3, c = idx & 7;
                cp16(sb + (uint32_t)(r * PITCH + c * 8) * 2,
                     A + Abase + (size_t)r * K + k0 + c * 8);
            } else {
                int j = idx - 1024;
                int r = j >> 3, c = j & 7;
                cp16(sb + (uint32_t)(A_MAT + r * PITCH + c * 8) * 2,
                     B + Bbase + (size_t)r * K + k0 + c * 8);
            }
        }
    };

    float acc[4][4][4];
#pragma unroll
    for (int i = 0; i < 4; i++)
#pragma unroll
        for (int j = 0; j < 4; j++)
#pragma unroll
            for (int v = 0; v < 4; v++) acc[i][j][v] = 0.f;

    const uint32_t a_off = (uint32_t)((wm * 64 + (lane & 15)) * PITCH) * 2 + (lane >> 4) * 16;
    const uint32_t b_off4 = (uint32_t)((wn * 32 + ((lane >> 4) & 1) * 8 + (lane & 7)) * PITCH) * 2
                          + ((lane >> 3) & 1) * 16;

    const int nch = K >> 6;
    load_stage(0, 0); cp_commit();
    load_stage(1, 1); cp_commit();

    for (int c = 0; c < nch; c++) {
        cp_wait<1>();
        __syncthreads();
        if (c + 2 < nch) load_stage(c + 2, (c + 2) % 3);
        cp_commit();

        const uint32_t Ahs = sbase + (c % 3) * STAGE_B;
        const uint32_t Bhs = Ahs + A_MAT * 2;

#pragma unroll
        for (int kk = 0; kk < 64; kk += 16) {
            uint32_t bf[4][2];
#pragma unroll
            for (int p = 0; p < 2; p++) {
                uint32_t t4[4];
                ldsm_x4(t4, Bhs + b_off4 + (uint32_t)(p * 16 * PITCH) * 2 + kk * 2);
                bf[2 * p][0]     = t4[0];
                bf[2 * p][1]     = t4[1];
                bf[2 * p + 1][0] = t4[2];
                bf[2 * p + 1][1] = t4[3];
            }
            uint32_t af[2][4];
            ldsm_x4(af[0], Ahs + a_off + kk * 2);
#pragma unroll
            for (int mt = 0; mt < 4; mt++) {
                if (mt < 3)
                    ldsm_x4(af[(mt + 1) & 1],
                            Ahs + a_off + (uint32_t)((mt + 1) * 16 * PITCH) * 2 + kk * 2);
#pragma unroll
                for (int nt = 0; nt < 4; nt++)
                    mma_f16(acc[mt][nt], af[mt & 1], bf[nt]);
            }
        }
    }

#pragma unroll
    for (int mt = 0; mt < 4; mt++) {
#pragma unroll
        for (int nt = 0; nt < 4; nt++) {
            const int col = bx * 128 + wn * 32 + nt * 8 + tig * 2;
            const float2 bv = *(const float2*)&bias[col];
            const int row0 = by * 128 + wm * 64 + mt * 16 + gid;
#pragma unroll
            for (int half = 0; half < 2; half++) {
                const int row = row0 + half * 8;
                float v0 = acc[mt][nt][half * 2]     + bv.x;
                float v1 = acc[mt][nt][half * 2 + 1] + bv.y;
                if (RELU) { v0 = fmaxf(v0, 0.f); v1 = fmaxf(v1, 0.f); }
                const size_t o = (size_t)row * N + col;
                __half2 hp;
                hp.x = __float2half_rn(v0);
                hp.y = __float2half_rn(v1);
                *(__half2*)(Ch + o) = hp;
            }
        }
    }
}

// ---------------- fused fp32->fp16 conversions (ILP 2, 512 thr) ----------
#define N4_X   1048576
#define N4_IW  786432
#define N4_OW  262144
#define N4_W1  1048576
#define N4_W2  1048576
#define N4_TOT 4194304

__global__ __launch_bounds__(512)
void cvt_all(const float* __restrict__ x,  __half* __restrict__ xh,
             const float* __restrict__ iw, __half* __restrict__ iwh,
             const float* __restrict__ ow, __half* __restrict__ owh,
             const float* __restrict__ w1, __half* __restrict__ w1h,
             const float* __restrict__ w2, __half* __restrict__ w2h)
{
    auto locate = [&](int i, const float*& s, __half*& d, int& j) {
        if      (i < N4_X)                         { s = x;  d = xh;  j = i; }
        else if (i < N4_X + N4_IW)                 { s = iw; d = iwh; j = i - N4_X; }
        else if (i < N4_X + N4_IW + N4_OW)         { s = ow; d = owh; j = i - N4_X - N4_IW; }
        else if (i < N4_X + N4_IW + N4_OW + N4_W1) { s = w1; d = w1h; j = i - N4_X - N4_IW - N4_OW; }
        else                                       { s = w2; d = w2h; j = i - N4_X - N4_IW - N4_OW - N4_W1; }
    };
    const int i0 = blockIdx.x * 1024 + threadIdx.x;
    const int i1 = i0 + 512;

    const float* s0; __half* d0; int j0;
    const float* s1; __half* d1; int j1;
    bool v0 = i0 < N4_TOT, v1 = i1 < N4_TOT;
    float4 a4, b4;
    if (v0) { locate(i0, s0, d0, j0); a4 = ((const float4*)s0)[j0]; }
    if (v1) { locate(i1, s1, d1, j1); b4 = ((const float4*)s1)[j1]; }

    if (v0) {
        __half2 a, b;
        a.x = __float2half_rn(a4.x); a.y = __float2half_rn(a4.y);
        b.x = __float2half_rn(a4.z); b.y = __float2half_rn(a4.w);
        ((__half2*)d0)[j0*2]   = a;
        ((__half2*)d0)[j0*2+1] = b;
    }
    if (v1) {
        __half2 a, b;
        a.x = __float2half_rn(b4.x); a.y = __float2half_rn(b4.y);
        b.x = __float2half_rn(b4.z); b.y = __float2half_rn(b4.w);
        ((__half2*)d1)[j1*2]   = a;
        ((__half2*)d1)[j1*2+1] = b;
    }
}

// ---------------- MMA banded flash attention, 64-key stages, 3-stage pipe ----
#define ATTN_SMEM ((128 + 3 * 128) * PITCH * 2)   // 73728 bytes

__global__ __launch_bounds__(256)
void attn_mma(const __half* __restrict__ qkvh, __half* __restrict__ outh)
{
    extern __shared__ __align__(16) __half asm_dyn[];
    const uint32_t sQ = smem_u32(asm_dyn);

    const int tid = threadIdx.x, warp = tid >> 5, lane = tid & 31;
    const int gid = lane >> 2, tig = lane & 3;
    const int b = blockIdx.z, h = blockIdx.y, q0 = blockIdx.x * 128;
    const __half* base = qkvh + (size_t)b * SS * (3 * DD);

    const int row0 = q0 + warp * 16 + gid;
    const int row1 = row0 + 8;
    const int klo = max(q0 - WIN, 0);
    const int khi = min(q0 + 127 + WIN, SS - 1);
    const int ntiles = (khi - klo + 1) >> 6;

    auto load_kv = [&](int it, int s) {
        const int kt = klo + it * 64;
        const uint32_t sK = sQ + (uint32_t)(128 + s * 128) * PITCH * 2;
        const uint32_t sV = sK + (uint32_t)64 * PITCH * 2;
#pragma unroll
        for (int i = 0; i < 4; i++) {
            int idx = i * 256 + tid;
            int r = (idx & 511) >> 3, c = idx & 7;
            size_t grow = (size_t)(kt + r) * (3 * DD) + h * HD + c * 8;
            if (idx < 512)
                cp16(sK + (uint32_t)(r * PITCH + c * 8) * 2, base + grow + DD);
            else
                cp16(sV + (uint32_t)(r * PITCH + c * 8) * 2, base + grow + 2 * DD);
        }
    };

#pragma unroll
    for (int i = 0; i < 4; i++) {
        int idx = i * 256 + tid;
        int r = idx >> 3, c = idx & 7;
        cp16(sQ + (uint32_t)(r * PITCH + c * 8) * 2,
             base + (size_t)(q0 + r) * (3 * DD) + h * HD + c * 8);
    }
    load_kv(0, 0); cp_commit();
    if (ntiles > 1) load_kv(1, 1);
    cp_commit();

    uint32_t qf[4][4];
    float o[8][4];
#pragma unroll
    for (int i = 0; i < 8; i++)
#pragma unroll
        for (int j = 0; j < 4; j++) o[i][j] = 0.f;
    float m0 = -1e30f, m1 = -1e30f, l0 = 0.f, l1 = 0.f;

    for (int it = 0; it < ntiles; it++) {
        cp_wait<1>();
        __syncthreads();
        if (it + 2 < ntiles) load_kv(it + 2, (it + 2) % 3);
        cp_commit();

        if (it == 0) {
            const uint32_t qa = sQ + (uint32_t)((warp * 16 + (lane & 15)) * PITCH) * 2 + (lane >> 4) * 16;
#pragma unroll
            for (int kc = 0; kc < 4; kc++) ldsm_x4(qf[kc], qa + kc * 32);
        }

        const int s = it % 3;
        const uint32_t sKst = sQ + (uint32_t)(128 + s * 128) * PITCH * 2;
        const uint32_t sVst = sKst + (uint32_t)64 * PITCH * 2;

#pragma unroll
        for (int half32 = 0; half32 < 2; half32++) {
            const int kt = klo + it * 64 + half32 * 32;
            const uint32_t sK = sKst + (uint32_t)(half32 * 32 * PITCH) * 2;
            const uint32_t sV = sVst + (uint32_t)(half32 * 32 * PITCH) * 2;

            float sc[4][4];
#pragma unroll
            for (int nt = 0; nt < 4; nt++)
#pragma unroll
                for (int j = 0; j < 4; j++) sc[nt][j] = 0.f;
#pragma unroll
            for (int nt = 0; nt < 4; nt++) {
                const uint32_t kbase = sK + (uint32_t)((nt * 8 + (lane & 7)) * PITCH) * 2 + (lane >> 3) * 16;
#pragma unroll
                for (int kp = 0; kp < 2; kp++) {
                    uint32_t kf[4];
                    ldsm_x4(kf, kbase + kp * 64);
                    mma_f16(sc[nt], qf[kp * 2],     &kf[0]);
                    mma_f16(sc[nt], qf[kp * 2 + 1], &kf[2]);
                }
            }

            float mx0 = -1e30f, mx1 = -1e30f;
#pragma unroll
            for (int nt = 0; nt < 4; nt++) {
                const int c0 = kt + nt * 8 + tig * 2, c1 = c0 + 1;
                float s2;
                s2 = sc[nt][0] * 0.125f;
                sc[nt][0] = (c0 >= row0 - WIN && c0 <= row0 + WIN && c0 <= khi) ? s2 : -1e30f;
                s2 = sc[nt][1] * 0.125f;
                sc[nt][1] = (c1 >= row0 - WIN && c1 <= row0 + WIN && c1 <= khi) ? s2 : -1e30f;
                s2 = sc[nt][2] * 0.125f;
                sc[nt][2] = (c0 >= row1 - WIN && c0 <= row1 + WIN && c0 <= khi) ? s2 : -1e30f;
                s2 = sc[nt][3] * 0.125f;
                sc[nt][3] = (c1 >= row1 - WIN && c1 <= row1 + WIN && c1 <= khi) ? s2 : -1e30f;
                mx0 = fmaxf(mx0, fmaxf(sc[nt][0], sc[nt][1]));
                mx1 = fmaxf(mx1, fmaxf(sc[nt][2], sc[nt][3]));
            }
            mx0 = fmaxf(mx0, __shfl_xor_sync(0xFFFFFFFFu, mx0, 1));
            mx0 = fmaxf(mx0, __shfl_xor_sync(0xFFFFFFFFu, mx0, 2));
            mx1 = fmaxf(mx1, __shfl_xor_sync(0xFFFFFFFFu, mx1, 1));
            mx1 = fmaxf(mx1, __shfl_xor_sync(0xFFFFFFFFu, mx1, 2));

            const float nm0 = fmaxf(m0, mx0), nm1 = fmaxf(m1, mx1);
            const float e0 = __expf(m0 - nm0), e1 = __expf(m1 - nm1);
            l0 *= e0; l1 *= e1;
#pragma unroll
            for (int ng = 0; ng < 8; ng++) {
                o[ng][0] *= e0; o[ng][1] *= e0;
                o[ng][2] *= e1; o[ng][3] *= e1;
            }
            m0 = nm0; m1 = nm1;

            uint32_t pf[2][4];
#pragma unroll
            for (int nt = 0; nt < 4; nt++) {
                float p0 = __expf(sc[nt][0] - nm0), p1 = __expf(sc[nt][1] - nm0);
                float p2 = __expf(sc[nt][2] - nm1), p3 = __expf(sc[nt][3] - nm1);
                l0 += p0 + p1; l1 += p2 + p3;
                __half2 h01 = __floats2half2_rn(p0, p1);
                __half2 h23 = __floats2half2_rn(p2, p3);
                pf[nt >> 1][(nt & 1) * 2 + 0] = *(uint32_t*)&h01;
                pf[nt >> 1][(nt & 1) * 2 + 1] = *(uint32_t*)&h23;
            }

#pragma unroll
            for (int np = 0; np < 4; np++) {
#pragma unroll
                for (int kc = 0; kc < 2; kc++) {
                    uint32_t vf[4];
                    ldsm_x4_t(vf, sV + (uint32_t)((kc * 16 + (lane & 15)) * PITCH) * 2 +
                                  (np * 2 + (lane >> 4)) * 16);
                    mma_f16(o[np * 2],     pf[kc], &vf[0]);
                    mma_f16(o[np * 2 + 1], pf[kc], &vf[2]);
                }
            }
        }
    }

    l0 += __shfl_xor_sync(0xFFFFFFFFu, l0, 1);
    l0 += __shfl_xor_sync(0xFFFFFFFFu, l0, 2);
    l1 += __shfl_xor_sync(0xFFFFFFFFu, l1, 1);
    l1 += __shfl_xor_sync(0xFFFFFFFFu, l1, 2);
    const float inv0 = 1.f / l0, inv1 = 1.f / l1;
    __half* o0p = outh + (size_t)(b * SS + row0) * DD + h * HD + tig * 2;
    __half* o1p = outh + (size_t)(b * SS + row1) * DD + h * HD + tig * 2;
#pragma unroll
    for (int ng = 0; ng < 8; ng++) {
        __half2 a = __floats2half2_rn(o[ng][0] * inv0, o[ng][1] * inv0);
        __half2 c = __floats2half2_rn(o[ng][2] * inv1, o[ng][3] * inv1);
        *(__half2*)(o0p + ng * 8) = a;
        *(__half2*)(o1p + ng * 8) = c;
    }
}

// ---------------- fused residual + LayerNorm (fp16 residual operand) ---------
__global__ __launch_bounds__(256)
void ln_kernel(const float* __restrict__ A, const __half* __restrict__ Rh,
               const float* __restrict__ g, const float* __restrict__ be,
               float* __restrict__ out, __half* __restrict__ oh)
{
    const int row = blockIdx.x;
    const int t = threadIdx.x;
    const size_t base = (size_t)row * DD;

    float4 av = *(const float4*)(A + base + t * 4);
    __half2 r01 = *(const __half2*)(Rh + base + t * 4);
    __half2 r23 = *(const __half2*)(Rh + base + t * 4 + 2);
    float2 rlo = __half22float2(r01);
    float2 rhi = __half22float2(r23);
    float4 v = make_float4(av.x + rlo.x, av.y + rlo.y, av.z + rhi.x, av.w + rhi.y);

    float s = v.x + v.y + v.z + v.w;
    float q = v.x * v.x + v.y * v.y + v.z * v.z + v.w * v.w;
#pragma unroll
    for (int off = 16; off > 0; off >>= 1) {
        s += __shfl_xor_sync(0xFFFFFFFFu, s, off);
        q += __shfl_xor_sync(0xFFFFFFFFu, q, off);
    }
    __shared__ float ss[8], sq[8];
    __shared__ float mu_s, inv_s;
    if ((t & 31) == 0) { ss[t >> 5] = s; sq[t >> 5] = q; }
    __syncthreads();
    if (t == 0) {
        float S = 0.f, Q = 0.f;
#pragma unroll
        for (int i = 0; i < 8; i++) { S += ss[i]; Q += sq[i]; }
        float mu = S * (1.f / DD);
        float var = Q * (1.f / DD) - mu * mu;
        mu_s = mu;
        inv_s = rsqrtf(var + 1e-5f);
    }
    __syncthreads();
    const float mu = mu_s, inv = inv_s;

    float4 gv = *(const float4*)(g + t * 4);
    float4 bv = *(const float4*)(be + t * 4);
    float4 o;
    o.x = (v.x - mu) * inv * gv.x + bv.x;
    o.y = (v.y - mu) * inv * gv.y + bv.y;
    o.z = (v.z - mu) * inv * gv.z + bv.z;
    o.w = (v.w - mu) * inv * gv.w + bv.w;
    *(float4*)(out + base + t * 4) = o;

    if (oh != nullptr) {
        __half2 h0, h1;
        h0.x = __float2half_rn(o.x); h0.y = __float2half_rn(o.y);
        h1.x = __float2half_rn(o.z); h1.y = __float2half_rn(o.w);
        *(__half2*)(oh + base + t * 4)     = h0;
        *(__half2*)(oh + base + t * 4 + 2) = h1;
    }
}

// ---------------- host ----------------
extern "C" void kernel_launch(void* const* d_in, const int* in_sizes, int n_in,
                              void* d_out, int out_size)
{
    (void)in_sizes; (void)n_in; (void)out_size;
    const float* x     = (const float*)d_in[0];
    const float* in_w  = (const float*)d_in[1];
    const float* in_b  = (const float*)d_in[2];
    const float* out_w = (const float*)d_in[3];
    const float* out_b = (const float*)d_in[4];
    const float* ln1g  = (const float*)d_in[5];
    const float* ln1b  = (const float*)d_in[6];
    const float* w1    = (const float*)d_in[7];
    const float* b1    = (const float*)d_in[8];
    const float* w2    = (const float*)d_in[9];
    const float* b2    = (const float*)d_in[10];
    const float* ln2g  = (const float*)d_in[11];
    const float* ln2b  = (const float*)d_in[12];
    float* out = (float*)d_out;

    float *x2;
    __half *tmph, *qkvh, *xh, *ath, *x2h, *ffh, *iwh, *owh, *w1h, *w2h;
    cudaGetSymbolAddress((void**)&tmph, g_tmph);
    cudaGetSymbolAddress((void**)&x2,   g_x2);
    cudaGetSymbolAddress((void**)&qkvh, g_qkvh);
    cudaGetSymbolAddress((void**)&xh,   g_x_h);
    cudaGetSymbolAddress((void**)&ath,  g_at_h);
    cudaGetSymbolAddress((void**)&x2h,  g_x2_h);
    cudaGetSymbolAddress((void**)&ffh,  g_ff_h);
    cudaGetSymbolAddress((void**)&iwh,  g_iw_h);
    cudaGetSymbolAddress((void**)&owh,  g_ow_h);
    cudaGetSymbolAddress((void**)&w1h,  g_w1_h);
    cudaGetSymbolAddress((void**)&w2h,  g_w2_h);

    cudaFuncSetAttribute(gemm_f16<false, true>,
                         cudaFuncAttributeMaxDynamicSharedMemorySize, GEMM_SMEM);
    cudaFuncSetAttribute(gemm_f16<true, true>,
                         cudaFuncAttributeMaxDynamicSharedMemorySize, GEMM_SMEM);
    cudaFuncSetAttribute(attn_mma,
                         cudaFuncAttributeMaxDynamicSharedMemorySize, ATTN_SMEM);

    cvt_all<<<(N4_TOT + 1023) / 1024, 512>>>(x, xh, in_w, iwh, out_w, owh, w1, w1h, w2, w2h);

    // 1. QKV projection -> fp16 qkv
    gemm_f16<false, true><<<dim3(3 * DD / 128, MTOT / 128), 256, GEMM_SMEM>>>(
        xh, iwh, in_b, qkvh, MTOT, 3 * DD, DD);
    // 2. MMA attention -> fp16 (64-key stages)
    attn_mma<<<dim3(SS / 128, HH, BB), 256, ATTN_SMEM>>>(qkvh, ath);
    // 3. out_proj -> fp16 tmp
    gemm_f16<false, true><<<dim3(DD / 128, MTOT / 128), 256, GEMM_SMEM>>>(
        ath, owh, out_b, tmph, MTOT, DD, DD);
    // 4. ln1 (x fp32 + tmp fp16) -> fp32 + fp16
    ln_kernel<<<MTOT, 256>>>(x, tmph, ln1g, ln1b, x2, x2h);
    // 5. ffn1 (relu) -> fp16
    gemm_f16<true, true><<<dim3(DFF / 128, MTOT / 128), 256, GEMM_SMEM>>>(
        x2h, w1h, b1, ffh, MTOT, DFF, DD);
    // 6. ffn2 -> fp16 tmp
    gemm_f16<false, true><<<dim3(DD / 128, MTOT / 128), 256, GEMM_SMEM>>>(
        ffh, w2h, b2, tmph, MTOT, DD, DFF);
    // 7. ln2 (x2 fp32 + tmp fp16) -> final fp32 out
    ln_kernel<<<MTOT, 256>>>(x2, tmph, ln2g, ln2b, out, nullptr);
}

// round 16
// speedup vs baseline: 1.1415x; 1.0010x over previous
#include <cuda_runtime.h>
#include <cuda_fp16.h>
#include <math.h>
#include <stdint.h>

#define BB   2
#define SS   2048
#define DD   1024
#define HH   16
#define HD   64
#define DFF  4096
#define WIN  128
#define MTOT (BB * SS)

// ---------------- device scratch ----------------
__device__ __half g_tmph[(size_t)MTOT * DD];     // out_proj / ffn2 out (fp16)
__device__ __half g_qkvh[(size_t)MTOT * 3 * DD];
__device__ __half g_x_h [(size_t)MTOT * DD];
__device__ __half g_at_h[(size_t)MTOT * DD];
__device__ __half g_x2_h[(size_t)MTOT * DD];
__device__ __half g_ff_h[(size_t)MTOT * DFF];
__device__ __half g_iw_h[(size_t)3*DD*DD];
__device__ __half g_ow_h[(size_t)DD*DD];
__device__ __half g_w1_h[(size_t)DFF*DD];
__device__ __half g_w2_h[(size_t)DD*DFF];

// ---------------- PTX helpers ----------------
__device__ __forceinline__ uint32_t smem_u32(const void* p) {
    uint32_t a;
    asm("{ .reg .u64 t; cvta.to.shared.u64 t, %1; cvt.u32.u64 %0, t; }" : "=r"(a) : "l"(p));
    return a;
}
__device__ __forceinline__ void cp16(uint32_t dst, const void* src) {
    asm volatile("cp.async.cg.shared.global [%0], [%1], 16;" :: "r"(dst), "l"(src));
}
__device__ __forceinline__ void cp_commit() {
    asm volatile("cp.async.commit_group;" ::: "memory");
}
template<int N>
__device__ __forceinline__ void cp_wait() {
    asm volatile("cp.async.wait_group %0;" :: "n"(N) : "memory");
}
__device__ __forceinline__ void mma_f16(float* c, const uint32_t* a, const uint32_t* b) {
    asm volatile(
        "mma.sync.aligned.m16n8k16.row.col.f32.f16.f16.f32 "
        "{%0,%1,%2,%3}, {%4,%5,%6,%7}, {%8,%9}, {%0,%1,%2,%3};"
        : "+f"(c[0]), "+f"(c[1]), "+f"(c[2]), "+f"(c[3])
        : "r"(a[0]), "r"(a[1]), "r"(a[2]), "r"(a[3]), "r"(b[0]), "r"(b[1]));
}
__device__ __forceinline__ void ldsm_x4(uint32_t* r, uint32_t addr) {
    asm volatile("ldmatrix.sync.aligned.m8n8.x4.shared.b16 {%0,%1,%2,%3}, [%4];"
                 : "=r"(r[0]), "=r"(r[1]), "=r"(r[2]), "=r"(r[3]) : "r"(addr));
}
__device__ __forceinline__ void ldsm_x4_t(uint32_t* r, uint32_t addr) {
    asm volatile("ldmatrix.sync.aligned.m8n8.x4.trans.shared.b16 {%0,%1,%2,%3}, [%4];"
                 : "=r"(r[0]), "=r"(r[1]), "=r"(r[2]), "=r"(r[3]) : "r"(addr));
}

// ---------------- fp32-accumulate GEMM (at the mma.sync floor) ----------------
#define PITCH   72
#define A_MAT   (128 * PITCH)
#define B_MAT   (128 * PITCH)
#define STAGE_E (A_MAT + B_MAT)
#define STAGE_B (STAGE_E * 2)
#define GEMM_SMEM (3 * STAGE_B)

template<bool RELU>
__global__ __launch_bounds__(256, 2)
void gemm_f16(const __half* __restrict__ A, const __half* __restrict__ B,
              const float* __restrict__ bias, __half* __restrict__ Ch,
              int M, int N, int K)
{
    extern __shared__ __align__(16) __half sm[];
    const uint32_t sbase = smem_u32(sm);
    const int tid  = threadIdx.x;
    const int warp = tid >> 5, lane = tid & 31;
    const int gid  = lane >> 2, tig = lane & 3;
    const int wm   = warp >> 2, wn = warp & 3;
    const int bx = blockIdx.x, by = blockIdx.y;

    const size_t Abase = (size_t)(by * 128) * K;
    const size_t Bbase = (size_t)(bx * 128) * K;

    auto load_stage = [&](int chunk, int s) {
        const int k0 = chunk * 64;
        const uint32_t sb = sbase + s * STAGE_B;
#pragma unroll
        for (int i = 0; i < 8; i++) {
            int idx = i * 256 + tid;
            if (idx < 1024) {
                int r = idx >> 3, c = idx & 7;
                cp16(sb + (uint32_t)(r * PITCH + c * 8) * 2,
                     A + Abase + (size_t)r * K + k0 + c * 8);
            } else {
                int j = idx - 1024;
                int r = j >> 3, c = j & 7;
                cp16(sb + (uint32_t)(A_MAT + r * PITCH + c * 8) * 2,
                     B + Bbase + (size_t)r * K + k0 + c * 8);
            }
        }
    };

    float acc[4][4][4];
#pragma unroll
    for (int i = 0; i < 4; i++)
#pragma unroll
        for (int j = 0; j < 4; j++)
#pragma unroll
            for (int v = 0; v < 4; v++) acc[i][j][v] = 0.f;

    const uint32_t a_off = (uint32_t)((wm * 64 + (lane & 15)) * PITCH) * 2 + (lane >> 4) * 16;
    const uint32_t b_off4 = (uint32_t)((wn * 32 + ((lane >> 4) & 1) * 8 + (lane & 7)) * PITCH) * 2
                          + ((lane >> 3) & 1) * 16;

    const int nch = K >> 6;
    load_stage(0, 0); cp_commit();
    load_stage(1, 1); cp_commit();

    for (int c = 0; c < nch; c++) {
        cp_wait<1>();
        __syncthreads();
        if (c + 2 < nch) load_stage(c + 2, (c + 2) % 3);
        cp_commit();

        const uint32_t Ahs = sbase + (c % 3) * STAGE_B;
        const uint32_t Bhs = Ahs + A_MAT * 2;

#pragma unroll
        for (int kk = 0; kk < 64; kk += 16) {
            uint32_t bf[4][2];
#pragma unroll
            for (int p = 0; p < 2; p++) {
                uint32_t t4[4];
                ldsm_x4(t4, Bhs + b_off4 + (uint32_t)(p * 16 * PITCH) * 2 + kk * 2);
                bf[2 * p][0]     = t4[0];
                bf[2 * p][1]     = t4[1];
                bf[2 * p + 1][0] = t4[2];
                bf[2 * p + 1][1] = t4[3];
            }
            uint32_t af[2][4];
            ldsm_x4(af[0], Ahs + a_off + kk * 2);
#pragma unroll
            for (int mt = 0; mt < 4; mt++) {
                if (mt < 3)
                    ldsm_x4(af[(mt + 1) & 1],
                            Ahs + a_off + (uint32_t)((mt + 1) * 16 * PITCH) * 2 + kk * 2);
#pragma unroll
                for (int nt = 0; nt < 4; nt++)
                    mma_f16(acc[mt][nt], af[mt & 1], bf[nt]);
            }
        }
    }

#pragma unroll
    for (int mt = 0; mt < 4; mt++) {
#pragma unroll
        for (int nt = 0; nt < 4; nt++) {
            const int col = bx * 128 + wn * 32 + nt * 8 + tig * 2;
            const float2 bv = *(const float2*)&bias[col];
            const int row0 = by * 128 + wm * 64 + mt * 16 + gid;
#pragma unroll
            for (int half = 0; half < 2; half++) {
                const int row = row0 + half * 8;
                float v0 = acc[mt][nt][half * 2]     + bv.x;
                float v1 = acc[mt][nt][half * 2 + 1] + bv.y;
                if (RELU) { v0 = fmaxf(v0, 0.f); v1 = fmaxf(v1, 0.f); }
                const size_t o = (size_t)row * N + col;
                __half2 hp;
                hp.x = __float2half_rn(v0);
                hp.y = __float2half_rn(v1);
                *(__half2*)(Ch + o) = hp;
            }
        }
    }
}

// ---------------- fused fp32->fp16 conversions (ILP 2, 512 thr) ----------
#define N4_X   1048576
#define N4_IW  786432
#define N4_OW  262144
#define N4_W1  1048576
#define N4_W2  1048576
#define N4_TOT 4194304

__global__ __launch_bounds__(512)
void cvt_all(const float* __restrict__ x,  __half* __restrict__ xh,
             const float* __restrict__ iw, __half* __restrict__ iwh,
             const float* __restrict__ ow, __half* __restrict__ owh,
             const float* __restrict__ w1, __half* __restrict__ w1h,
             const float* __restrict__ w2, __half* __restrict__ w2h)
{
    auto locate = [&](int i, const float*& s, __half*& d, int& j) {
        if      (i < N4_X)                         { s = x;  d = xh;  j = i; }
        else if (i < N4_X + N4_IW)                 { s = iw; d = iwh; j = i - N4_X; }
        else if (i < N4_X + N4_IW + N4_OW)         { s = ow; d = owh; j = i - N4_X - N4_IW; }
        else if (i < N4_X + N4_IW + N4_OW + N4_W1) { s = w1; d = w1h; j = i - N4_X - N4_IW - N4_OW; }
        else                                       { s = w2; d = w2h; j = i - N4_X - N4_IW - N4_OW - N4_W1; }
    };
    const int i0 = blockIdx.x * 1024 + threadIdx.x;
    const int i1 = i0 + 512;

    const float* s0; __half* d0; int j0;
    const float* s1; __half* d1; int j1;
    bool v0 = i0 < N4_TOT, v1 = i1 < N4_TOT;
    float4 a4, b4;
    if (v0) { locate(i0, s0, d0, j0); a4 = ((const float4*)s0)[j0]; }
    if (v1) { locate(i1, s1, d1, j1); b4 = ((const float4*)s1)[j1]; }

    if (v0) {
        __half2 a, b;
        a.x = __float2half_rn(a4.x); a.y = __float2half_rn(a4.y);
        b.x = __float2half_rn(a4.z); b.y = __float2half_rn(a4.w);
        ((__half2*)d0)[j0*2]   = a;
        ((__half2*)d0)[j0*2+1] = b;
    }
    if (v1) {
        __half2 a, b;
        a.x = __float2half_rn(b4.x); a.y = __float2half_rn(b4.y);
        b.x = __float2half_rn(b4.z); b.y = __float2half_rn(b4.w);
        ((__half2*)d1)[j1*2]   = a;
        ((__half2*)d1)[j1*2+1] = b;
    }
}

// ---------------- MMA banded flash attention, 64-key stages, 3-stage pipe ----
#define ATTN_SMEM ((128 + 3 * 128) * PITCH * 2)   // 73728 bytes

__global__ __launch_bounds__(256)
void attn_mma(const __half* __restrict__ qkvh, __half* __restrict__ outh)
{
    extern __shared__ __align__(16) __half asm_dyn[];
    const uint32_t sQ = smem_u32(asm_dyn);

    const int tid = threadIdx.x, warp = tid >> 5, lane = tid & 31;
    const int gid = lane >> 2, tig = lane & 3;
    const int b = blockIdx.z, h = blockIdx.y, q0 = blockIdx.x * 128;
    const __half* base = qkvh + (size_t)b * SS * (3 * DD);

    const int row0 = q0 + warp * 16 + gid;
    const int row1 = row0 + 8;
    const int klo = max(q0 - WIN, 0);
    const int khi = min(q0 + 127 + WIN, SS - 1);
    const int ntiles = (khi - klo + 1) >> 6;

    auto load_kv = [&](int it, int s) {
        const int kt = klo + it * 64;
        const uint32_t sK = sQ + (uint32_t)(128 + s * 128) * PITCH * 2;
        const uint32_t sV = sK + (uint32_t)64 * PITCH * 2;
#pragma unroll
        for (int i = 0; i < 4; i++) {
            int idx = i * 256 + tid;
            int r = (idx & 511) >> 3, c = idx & 7;
            size_t grow = (size_t)(kt + r) * (3 * DD) + h * HD + c * 8;
            if (idx < 512)
                cp16(sK + (uint32_t)(r * PITCH + c * 8) * 2, base + grow + DD);
            else
                cp16(sV + (uint32_t)(r * PITCH + c * 8) * 2, base + grow + 2 * DD);
        }
    };

#pragma unroll
    for (int i = 0; i < 4; i++) {
        int idx = i * 256 + tid;
        int r = idx >> 3, c = idx & 7;
        cp16(sQ + (uint32_t)(r * PITCH + c * 8) * 2,
             base + (size_t)(q0 + r) * (3 * DD) + h * HD + c * 8);
    }
    load_kv(0, 0); cp_commit();
    if (ntiles > 1) load_kv(1, 1);
    cp_commit();

    uint32_t qf[4][4];
    float o[8][4];
#pragma unroll
    for (int i = 0; i < 8; i++)
#pragma unroll
        for (int j = 0; j < 4; j++) o[i][j] = 0.f;
    float m0 = -1e30f, m1 = -1e30f, l0 = 0.f, l1 = 0.f;

    for (int it = 0; it < ntiles; it++) {
        cp_wait<1>();
        __syncthreads();
        if (it + 2 < ntiles) load_kv(it + 2, (it + 2) % 3);
        cp_commit();

        if (it == 0) {
            const uint32_t qa = sQ + (uint32_t)((warp * 16 + (lane & 15)) * PITCH) * 2 + (lane >> 4) * 16;
#pragma unroll
            for (int kc = 0; kc < 4; kc++) ldsm_x4(qf[kc], qa + kc * 32);
        }

        const int s = it % 3;
        const uint32_t sKst = sQ + (uint32_t)(128 + s * 128) * PITCH * 2;
        const uint32_t sVst = sKst + (uint32_t)64 * PITCH * 2;

#pragma unroll
        for (int half32 = 0; half32 < 2; half32++) {
            const int kt = klo + it * 64 + half32 * 32;
            const uint32_t sK = sKst + (uint32_t)(half32 * 32 * PITCH) * 2;
            const uint32_t sV = sVst + (uint32_t)(half32 * 32 * PITCH) * 2;

            float sc[4][4];
#pragma unroll
            for (int nt = 0; nt < 4; nt++)
#pragma unroll
                for (int j = 0; j < 4; j++) sc[nt][j] = 0.f;
#pragma unroll
            for (int nt = 0; nt < 4; nt++) {
                const uint32_t kbase = sK + (uint32_t)((nt * 8 + (lane & 7)) * PITCH) * 2 + (lane >> 3) * 16;
#pragma unroll
                for (int kp = 0; kp < 2; kp++) {
                    uint32_t kf[4];
                    ldsm_x4(kf, kbase + kp * 64);
                    mma_f16(sc[nt], qf[kp * 2],     &kf[0]);
                    mma_f16(sc[nt], qf[kp * 2 + 1], &kf[2]);
                }
            }

            float mx0 = -1e30f, mx1 = -1e30f;
#pragma unroll
            for (int nt = 0; nt < 4; nt++) {
                const int c0 = kt + nt * 8 + tig * 2, c1 = c0 + 1;
                float s2;
                s2 = sc[nt][0] * 0.125f;
                sc[nt][0] = (c0 >= row0 - WIN && c0 <= row0 + WIN && c0 <= khi) ? s2 : -1e30f;
                s2 = sc[nt][1] * 0.125f;
                sc[nt][1] = (c1 >= row0 - WIN && c1 <= row0 + WIN && c1 <= khi) ? s2 : -1e30f;
                s2 = sc[nt][2] * 0.125f;
                sc[nt][2] = (c0 >= row1 - WIN && c0 <= row1 + WIN && c0 <= khi) ? s2 : -1e30f;
                s2 = sc[nt][3] * 0.125f;
                sc[nt][3] = (c1 >= row1 - WIN && c1 <= row1 + WIN && c1 <= khi) ? s2 : -1e30f;
                mx0 = fmaxf(mx0, fmaxf(sc[nt][0], sc[nt][1]));
                mx1 = fmaxf(mx1, fmaxf(sc[nt][2], sc[nt][3]));
            }
            mx0 = fmaxf(mx0, __shfl_xor_sync(0xFFFFFFFFu, mx0, 1));
            mx0 = fmaxf(mx0, __shfl_xor_sync(0xFFFFFFFFu, mx0, 2));
            mx1 = fmaxf(mx1, __shfl_xor_sync(0xFFFFFFFFu, mx1, 1));
            mx1 = fmaxf(mx1, __shfl_xor_sync(0xFFFFFFFFu, mx1, 2));

            const float nm0 = fmaxf(m0, mx0), nm1 = fmaxf(m1, mx1);
            const float e0 = __expf(m0 - nm0), e1 = __expf(m1 - nm1);
            l0 *= e0; l1 *= e1;
#pragma unroll
            for (int ng = 0; ng < 8; ng++) {
                o[ng][0] *= e0; o[ng][1] *= e0;
                o[ng][2] *= e1; o[ng][3] *= e1;
            }
            m0 = nm0; m1 = nm1;

            uint32_t pf[2][4];
#pragma unroll
            for (int nt = 0; nt < 4; nt++) {
                float p0 = __expf(sc[nt][0] - nm0), p1 = __expf(sc[nt][1] - nm0);
                float p2 = __expf(sc[nt][2] - nm1), p3 = __expf(sc[nt][3] - nm1);
                l0 += p0 + p1; l1 += p2 + p3;
                __half2 h01 = __floats2half2_rn(p0, p1);
                __half2 h23 = __floats2half2_rn(p2, p3);
                pf[nt >> 1][(nt & 1) * 2 + 0] = *(uint32_t*)&h01;
                pf[nt >> 1][(nt & 1) * 2 + 1] = *(uint32_t*)&h23;
            }

#pragma unroll
            for (int np = 0; np < 4; np++) {
#pragma unroll
                for (int kc = 0; kc < 2; kc++) {
                    uint32_t vf[4];
                    ldsm_x4_t(vf, sV + (uint32_t)((kc * 16 + (lane & 15)) * PITCH) * 2 +
                                  (np * 2 + (lane >> 4)) * 16);
                    mma_f16(o[np * 2],     pf[kc], &vf[0]);
                    mma_f16(o[np * 2 + 1], pf[kc], &vf[2]);
                }
            }
        }
    }

    l0 += __shfl_xor_sync(0xFFFFFFFFu, l0, 1);
    l0 += __shfl_xor_sync(0xFFFFFFFFu, l0, 2);
    l1 += __shfl_xor_sync(0xFFFFFFFFu, l1, 1);
    l1 += __shfl_xor_sync(0xFFFFFFFFu, l1, 2);
    const float inv0 = 1.f / l0, inv1 = 1.f / l1;
    __half* o0p = outh + (size_t)(b * SS + row0) * DD + h * HD + tig * 2;
    __half* o1p = outh + (size_t)(b * SS + row1) * DD + h * HD + tig * 2;
#pragma unroll
    for (int ng = 0; ng < 8; ng++) {
        __half2 a = __floats2half2_rn(o[ng][0] * inv0, o[ng][1] * inv0);
        __half2 c = __floats2half2_rn(o[ng][2] * inv1, o[ng][3] * inv1);
        *(__half2*)(o0p + ng * 8) = a;
        *(__half2*)(o1p + ng * 8) = c;
    }
}

// ---------------- fused residual + LayerNorm --------------------------------
// AFP16: base operand fp16 (else fp32).  WF32OUT: write fp32 out (else fp16 oh).
template<bool AFP16, bool WF32OUT>
__global__ __launch_bounds__(256)
void ln_kernel(const float* __restrict__ Af, const __half* __restrict__ Ah,
               const __half* __restrict__ Rh,
               const float* __restrict__ g, const float* __restrict__ be,
               float* __restrict__ out, __half* __restrict__ oh)
{
    const int row = blockIdx.x;
    const int t = threadIdx.x;
    const size_t base = (size_t)row * DD;

    float4 av;
    if (AFP16) {
        __half2 a01 = *(const __half2*)(Ah + base + t * 4);
        __half2 a23 = *(const __half2*)(Ah + base + t * 4 + 2);
        float2 lo = __half22float2(a01);
        float2 hi = __half22float2(a23);
        av = make_float4(lo.x, lo.y, hi.x, hi.y);
    } else {
        av = *(const float4*)(Af + base + t * 4);
    }
    __half2 r01 = *(const __half2*)(Rh + base + t * 4);
    __half2 r23 = *(const __half2*)(Rh + base + t * 4 + 2);
    float2 rlo = __half22float2(r01);
    float2 rhi = __half22float2(r23);
    float4 v = make_float4(av.x + rlo.x, av.y + rlo.y, av.z + rhi.x, av.w + rhi.y);

    float s = v.x + v.y + v.z + v.w;
    float q = v.x * v.x + v.y * v.y + v.z * v.z + v.w * v.w;
#pragma unroll
    for (int off = 16; off > 0; off >>= 1) {
        s += __shfl_xor_sync(0xFFFFFFFFu, s, off);
        q += __shfl_xor_sync(0xFFFFFFFFu, q, off);
    }
    __shared__ float ss[8], sq[8];
    __shared__ float mu_s, inv_s;
    if ((t & 31) == 0) { ss[t >> 5] = s; sq[t >> 5] = q; }
    __syncthreads();
    if (t == 0) {
        float S = 0.f, Q = 0.f;
#pragma unroll
        for (int i = 0; i < 8; i++) { S += ss[i]; Q += sq[i]; }
        float mu = S * (1.f / DD);
        float var = Q * (1.f / DD) - mu * mu;
        mu_s = mu;
        inv_s = rsqrtf(var + 1e-5f);
    }
    __syncthreads();
    const float mu = mu_s, inv = inv_s;

    float4 gv = *(const float4*)(g + t * 4);
    float4 bv = *(const float4*)(be + t * 4);
    float4 o;
    o.x = (v.x - mu) * inv * gv.x + bv.x;
    o.y = (v.y - mu) * inv * gv.y + bv.y;
    o.z = (v.z - mu) * inv * gv.z + bv.z;
    o.w = (v.w - mu) * inv * gv.w + bv.w;

    if (WF32OUT) {
        *(float4*)(out + base + t * 4) = o;
    } else {
        __half2 h0, h1;
        h0.x = __float2half_rn(o.x); h0.y = __float2half_rn(o.y);
        h1.x = __float2half_rn(o.z); h1.y = __float2half_rn(o.w);
        *(__half2*)(oh + base + t * 4)     = h0;
        *(__half2*)(oh + base + t * 4 + 2) = h1;
    }
}

// ---------------- host ----------------
extern "C" void kernel_launch(void* const* d_in, const int* in_sizes, int n_in,
                              void* d_out, int out_size)
{
    (void)in_sizes; (void)n_in; (void)out_size;
    const float* x     = (const float*)d_in[0];
    const float* in_w  = (const float*)d_in[1];
    const float* in_b  = (const float*)d_in[2];
    const float* out_w = (const float*)d_in[3];
    const float* out_b = (const float*)d_in[4];
    const float* ln1g  = (const float*)d_in[5];
    const float* ln1b  = (const float*)d_in[6];
    const float* w1    = (const float*)d_in[7];
    const float* b1    = (const float*)d_in[8];
    const float* w2    = (const float*)d_in[9];
    const float* b2    = (const float*)d_in[10];
    const float* ln2g  = (const float*)d_in[11];
    const float* ln2b  = (const float*)d_in[12];
    float* out = (float*)d_out;

    __half *tmph, *qkvh, *xh, *ath, *x2h, *ffh, *iwh, *owh, *w1h, *w2h;
    cudaGetSymbolAddress((void**)&tmph, g_tmph);
    cudaGetSymbolAddress((void**)&qkvh, g_qkvh);
    cudaGetSymbolAddress((void**)&xh,   g_x_h);
    cudaGetSymbolAddress((void**)&ath,  g_at_h);
    cudaGetSymbolAddress((void**)&x2h,  g_x2_h);
    cudaGetSymbolAddress((void**)&ffh,  g_ff_h);
    cudaGetSymbolAddress((void**)&iwh,  g_iw_h);
    cudaGetSymbolAddress((void**)&owh,  g_ow_h);
    cudaGetSymbolAddress((void**)&w1h,  g_w1_h);
    cudaGetSymbolAddress((void**)&w2h,  g_w2_h);

    cudaFuncSetAttribute(gemm_f16<false>,
                         cudaFuncAttributeMaxDynamicSharedMemorySize, GEMM_SMEM);
    cudaFuncSetAttribute(gemm_f16<true>,
                         cudaFuncAttributeMaxDynamicSharedMemorySize, GEMM_SMEM);
    cudaFuncSetAttribute(attn_mma,
                         cudaFuncAttributeMaxDynamicSharedMemorySize, ATTN_SMEM);

    cvt_all<<<(N4_TOT + 1023) / 1024, 512>>>(x, xh, in_w, iwh, out_w, owh, w1, w1h, w2, w2h);

    // 1. QKV projection -> fp16 qkv
    gemm_f16<false><<<dim3(3 * DD / 128, MTOT / 128), 256, GEMM_SMEM>>>(
        xh, iwh, in_b, qkvh, MTOT, 3 * DD, DD);
    // 2. MMA attention -> fp16 (64-key stages)
    attn_mma<<<dim3(SS / 128, HH, BB), 256, ATTN_SMEM>>>(qkvh, ath);
    // 3. out_proj -> fp16 tmp
    gemm_f16<false><<<dim3(DD / 128, MTOT / 128), 256, GEMM_SMEM>>>(
        ath, owh, out_b, tmph, MTOT, DD, DD);
    // 4. ln1 (x fp32 + tmp fp16) -> fp16 x2h only
    ln_kernel<false, false><<<MTOT, 256>>>(x, nullptr, tmph, ln1g, ln1b, nullptr, x2h);
    // 5. ffn1 (relu) -> fp16
    gemm_f16<true><<<dim3(DFF / 128, MTOT / 128), 256, GEMM_SMEM>>>(
        x2h, w1h, b1, ffh, MTOT, DFF, DD);
    // 6. ffn2 -> fp16 tmp
    gemm_f16<false><<<dim3(DD / 128, MTOT / 128), 256, GEMM_SMEM>>>(
        ffh, w2h, b2, tmph, MTOT, DD, DFF);
    // 7. ln2 (x2h fp16 + tmp fp16) -> final fp32 out
    ln_kernel<true, true><<<MTOT, 256>>>(nullptr, x2h, tmph, ln2g, ln2b, out, nullptr);
}

// round 17
// speedup vs baseline: 1.1473x; 1.0051x over previous
#include <cuda_runtime.h>
#include <cuda_fp16.h>
#include <math.h>
#include <stdint.h>

#define BB   2
#define SS   2048
#define DD   1024
#define HH   16
#define HD   64
#define DFF  4096
#define WIN  128
#define MTOT (BB * SS)

// ---------------- device scratch ----------------
__device__ __half g_tmph[(size_t)MTOT * DD];     // out_proj / ffn2 out (fp16)
__device__ __half g_qkvh[(size_t)MTOT * 3 * DD];
__device__ __half g_x_h [(size_t)MTOT * DD];
__device__ __half g_at_h[(size_t)MTOT * DD];
__device__ __half g_x2_h[(size_t)MTOT * DD];
__device__ __half g_ff_h[(size_t)MTOT * DFF];
__device__ __half g_iw_h[(size_t)3*DD*DD];
__device__ __half g_ow_h[(size_t)DD*DD];
__device__ __half g_w1_h[(size_t)DFF*DD];
__device__ __half g_w2_h[(size_t)DD*DFF];

// ---------------- PTX helpers ----------------
__device__ __forceinline__ uint32_t smem_u32(const void* p) {
    uint32_t a;
    asm("{ .reg .u64 t; cvta.to.shared.u64 t, %1; cvt.u32.u64 %0, t; }" : "=r"(a) : "l"(p));
    return a;
}
__device__ __forceinline__ void cp16(uint32_t dst, const void* src) {
    asm volatile("cp.async.cg.shared.global [%0], [%1], 16;" :: "r"(dst), "l"(src));
}
__device__ __forceinline__ void cp_commit() {
    asm volatile("cp.async.commit_group;" ::: "memory");
}
template<int N>
__device__ __forceinline__ void cp_wait() {
    asm volatile("cp.async.wait_group %0;" :: "n"(N) : "memory");
}
__device__ __forceinline__ void mma_f16(float* c, const uint32_t* a, const uint32_t* b) {
    asm volatile(
        "mma.sync.aligned.m16n8k16.row.col.f32.f16.f16.f32 "
        "{%0,%1,%2,%3}, {%4,%5,%6,%7}, {%8,%9}, {%0,%1,%2,%3};"
        : "+f"(c[0]), "+f"(c[1]), "+f"(c[2]), "+f"(c[3])
        : "r"(a[0]), "r"(a[1]), "r"(a[2]), "r"(a[3]), "r"(b[0]), "r"(b[1]));
}
__device__ __forceinline__ void ldsm_x4(uint32_t* r, uint32_t addr) {
    asm volatile("ldmatrix.sync.aligned.m8n8.x4.shared.b16 {%0,%1,%2,%3}, [%4];"
                 : "=r"(r[0]), "=r"(r[1]), "=r"(r[2]), "=r"(r[3]) : "r"(addr));
}
__device__ __forceinline__ void ldsm_x4_t(uint32_t* r, uint32_t addr) {
    asm volatile("ldmatrix.sync.aligned.m8n8.x4.trans.shared.b16 {%0,%1,%2,%3}, [%4];"
                 : "=r"(r[0]), "=r"(r[1]), "=r"(r[2]), "=r"(r[3]) : "r"(addr));
}

// ---------------- fp32-accumulate GEMM (at the mma.sync floor) ----------------
#define PITCH   72
#define A_MAT   (128 * PITCH)
#define B_MAT   (128 * PITCH)
#define STAGE_E (A_MAT + B_MAT)
#define STAGE_B (STAGE_E * 2)
#define GEMM_SMEM (3 * STAGE_B)

template<bool RELU>
__global__ __launch_bounds__(256, 2)
void gemm_f16(const __half* __restrict__ A, const __half* __restrict__ B,
              const float* __restrict__ bias, __half* __restrict__ Ch,
              int M, int N, int K)
{
    extern __shared__ __align__(16) __half sm[];
    const uint32_t sbase = smem_u32(sm);
    const int tid  = threadIdx.x;
    const int warp = tid >> 5, lane = tid & 31;
    const int gid  = lane >> 2, tig = lane & 3;
    const int wm   = warp >> 2, wn = warp & 3;
    const int bx = blockIdx.x, by = blockIdx.y;

    const size_t Abase = (size_t)(by * 128) * K;
    const size_t Bbase = (size_t)(bx * 128) * K;

    auto load_stage = [&](int chunk, int s) {
        const int k0 = chunk * 64;
        const uint32_t sb = sbase + s * STAGE_B;
#pragma unroll
        for (int i = 0; i < 8; i++) {
            int idx = i * 256 + tid;
            if (idx < 1024) {
                int r = idx >> 3, c = idx & 7;
                cp16(sb + (uint32_t)(r * PITCH + c * 8) * 2,
                     A + Abase + (size_t)r * K + k0 + c * 8);
            } else {
                int j = idx - 1024;
                int r = j >> 3, c = j & 7;
                cp16(sb + (uint32_t)(A_MAT + r * PITCH + c * 8) * 2,
                     B + Bbase + (size_t)r * K + k0 + c * 8);
            }
        }
    };

    float acc[4][4][4];
#pragma unroll
    for (int i = 0; i < 4; i++)
#pragma unroll
        for (int j = 0; j < 4; j++)
#pragma unroll
            for (int v = 0; v < 4; v++) acc[i][j][v] = 0.f;

    const uint32_t a_off = (uint32_t)((wm * 64 + (lane & 15)) * PITCH) * 2 + (lane >> 4) * 16;
    const uint32_t b_off4 = (uint32_t)((wn * 32 + ((lane >> 4) & 1) * 8 + (lane & 7)) * PITCH) * 2
                          + ((lane >> 3) & 1) * 16;

    const int nch = K >> 6;
    load_stage(0, 0); cp_commit();
    load_stage(1, 1); cp_commit();

    for (int c = 0; c < nch; c++) {
        cp_wait<1>();
        __syncthreads();
        if (c + 2 < nch) load_stage(c + 2, (c + 2) % 3);
        cp_commit();

        const uint32_t Ahs = sbase + (c % 3) * STAGE_B;
        const uint32_t Bhs = Ahs + A_MAT * 2;

#pragma unroll
        for (int kk = 0; kk < 64; kk += 16) {
            uint32_t bf[4][2];
#pragma unroll
            for (int p = 0; p < 2; p++) {
                uint32_t t4[4];
                ldsm_x4(t4, Bhs + b_off4 + (uint32_t)(p * 16 * PITCH) * 2 + kk * 2);
                bf[2 * p][0]     = t4[0];
                bf[2 * p][1]     = t4[1];
                bf[2 * p + 1][0] = t4[2];
                bf[2 * p + 1][1] = t4[3];
            }
            uint32_t af[2][4];
            ldsm_x4(af[0], Ahs + a_off + kk * 2);
#pragma unroll
            for (int mt = 0; mt < 4; mt++) {
                if (mt < 3)
                    ldsm_x4(af[(mt + 1) & 1],
                            Ahs + a_off + (uint32_t)((mt + 1) * 16 * PITCH) * 2 + kk * 2);
#pragma unroll
                for (int nt = 0; nt < 4; nt++)
                    mma_f16(acc[mt][nt], af[mt & 1], bf[nt]);
            }
        }
    }

#pragma unroll
    for (int mt = 0; mt < 4; mt++) {
#pragma unroll
        for (int nt = 0; nt < 4; nt++) {
            const int col = bx * 128 + wn * 32 + nt * 8 + tig * 2;
            const float2 bv = *(const float2*)&bias[col];
            const int row0 = by * 128 + wm * 64 + mt * 16 + gid;
#pragma unroll
            for (int half = 0; half < 2; half++) {
                const int row = row0 + half * 8;
                float v0 = acc[mt][nt][half * 2]     + bv.x;
                float v1 = acc[mt][nt][half * 2 + 1] + bv.y;
                if (RELU) { v0 = fmaxf(v0, 0.f); v1 = fmaxf(v1, 0.f); }
                const size_t o = (size_t)row * N + col;
                __half2 hp;
                hp.x = __float2half_rn(v0);
                hp.y = __float2half_rn(v1);
                *(__half2*)(Ch + o) = hp;
            }
        }
    }
}

// ---------------- fused fp32->fp16 conversions (ILP 2, 512 thr) ----------
#define N4_X   1048576
#define N4_IW  786432
#define N4_OW  262144
#define N4_W1  1048576
#define N4_W2  1048576
#define N4_TOT 4194304

__global__ __launch_bounds__(512)
void cvt_all(const float* __restrict__ x,  __half* __restrict__ xh,
             const float* __restrict__ iw, __half* __restrict__ iwh,
             const float* __restrict__ ow, __half* __restrict__ owh,
             const float* __restrict__ w1, __half* __restrict__ w1h,
             const float* __restrict__ w2, __half* __restrict__ w2h)
{
    auto locate = [&](int i, const float*& s, __half*& d, int& j) {
        if      (i < N4_X)                         { s = x;  d = xh;  j = i; }
        else if (i < N4_X + N4_IW)                 { s = iw; d = iwh; j = i - N4_X; }
        else if (i < N4_X + N4_IW + N4_OW)         { s = ow; d = owh; j = i - N4_X - N4_IW; }
        else if (i < N4_X + N4_IW + N4_OW + N4_W1) { s = w1; d = w1h; j = i - N4_X - N4_IW - N4_OW; }
        else                                       { s = w2; d = w2h; j = i - N4_X - N4_IW - N4_OW - N4_W1; }
    };
    const int i0 = blockIdx.x * 1024 + threadIdx.x;
    const int i1 = i0 + 512;

    const float* s0; __half* d0; int j0;
    const float* s1; __half* d1; int j1;
    bool v0 = i0 < N4_TOT, v1 = i1 < N4_TOT;
    float4 a4, b4;
    if (v0) { locate(i0, s0, d0, j0); a4 = ((const float4*)s0)[j0]; }
    if (v1) { locate(i1, s1, d1, j1); b4 = ((const float4*)s1)[j1]; }

    if (v0) {
        __half2 a, b;
        a.x = __float2half_rn(a4.x); a.y = __float2half_rn(a4.y);
        b.x = __float2half_rn(a4.z); b.y = __float2half_rn(a4.w);
        ((__half2*)d0)[j0*2]   = a;
        ((__half2*)d0)[j0*2+1] = b;
    }
    if (v1) {
        __half2 a, b;
        a.x = __float2half_rn(b4.x); a.y = __float2half_rn(b4.y);
        b.x = __float2half_rn(b4.z); b.y = __float2half_rn(b4.w);
        ((__half2*)d1)[j1*2]   = a;
        ((__half2*)d1)[j1*2+1] = b;
    }
}

// ---------------- MMA banded flash attention, 64-key stages, 2-stage pipe ----
// 2 stages -> 55.3KB smem -> 2 CTAs/SM (was 1).  Compute block unchanged.
#define ATTN_SMEM ((128 + 2 * 128) * PITCH * 2)   // 55296 bytes

__global__ __launch_bounds__(256, 2)
void attn_mma(const __half* __restrict__ qkvh, __half* __restrict__ outh)
{
    extern __shared__ __align__(16) __half asm_dyn[];
    const uint32_t sQ = smem_u32(asm_dyn);

    const int tid = threadIdx.x, warp = tid >> 5, lane = tid & 31;
    const int gid = lane >> 2, tig = lane & 3;
    const int b = blockIdx.z, h = blockIdx.y, q0 = blockIdx.x * 128;
    const __half* base = qkvh + (size_t)b * SS * (3 * DD);

    const int row0 = q0 + warp * 16 + gid;
    const int row1 = row0 + 8;
    const int klo = max(q0 - WIN, 0);
    const int khi = min(q0 + 127 + WIN, SS - 1);
    const int ntiles = (khi - klo + 1) >> 6;

    auto load_kv = [&](int it, int s) {
        const int kt = klo + it * 64;
        const uint32_t sK = sQ + (uint32_t)(128 + s * 128) * PITCH * 2;
        const uint32_t sV = sK + (uint32_t)64 * PITCH * 2;
#pragma unroll
        for (int i = 0; i < 4; i++) {
            int idx = i * 256 + tid;
            int r = (idx & 511) >> 3, c = idx & 7;
            size_t grow = (size_t)(kt + r) * (3 * DD) + h * HD + c * 8;
            if (idx < 512)
                cp16(sK + (uint32_t)(r * PITCH + c * 8) * 2, base + grow + DD);
            else
                cp16(sV + (uint32_t)(r * PITCH + c * 8) * 2, base + grow + 2 * DD);
        }
    };

    // prologue: Q + KV(0) in group 0
#pragma unroll
    for (int i = 0; i < 4; i++) {
        int idx = i * 256 + tid;
        int r = idx >> 3, c = idx & 7;
        cp16(sQ + (uint32_t)(r * PITCH + c * 8) * 2,
             base + (size_t)(q0 + r) * (3 * DD) + h * HD + c * 8);
    }
    load_kv(0, 0); cp_commit();

    uint32_t qf[4][4];
    float o[8][4];
#pragma unroll
    for (int i = 0; i < 8; i++)
#pragma unroll
        for (int j = 0; j < 4; j++) o[i][j] = 0.f;
    float m0 = -1e30f, m1 = -1e30f, l0 = 0.f, l1 = 0.f;

    for (int it = 0; it < ntiles; it++) {
        __syncthreads();                    // all warps done with slot it&1 (iter it-2? guard slot reuse)
        if (it + 1 < ntiles) load_kv(it + 1, (it + 1) & 1);
        cp_commit();                        // constant 1 group per iter
        cp_wait<1>();                       // stage it complete
        __syncthreads();

        if (it == 0) {
            const uint32_t qa = sQ + (uint32_t)((warp * 16 + (lane & 15)) * PITCH) * 2 + (lane >> 4) * 16;
#pragma unroll
            for (int kc = 0; kc < 4; kc++) ldsm_x4(qf[kc], qa + kc * 32);
        }

        const int s = it & 1;
        const uint32_t sKst = sQ + (uint32_t)(128 + s * 128) * PITCH * 2;
        const uint32_t sVst = sKst + (uint32_t)64 * PITCH * 2;

#pragma unroll
        for (int half32 = 0; half32 < 2; half32++) {
            const int kt = klo + it * 64 + half32 * 32;
            const uint32_t sK = sKst + (uint32_t)(half32 * 32 * PITCH) * 2;
            const uint32_t sV = sVst + (uint32_t)(half32 * 32 * PITCH) * 2;

            float sc[4][4];
#pragma unroll
            for (int nt = 0; nt < 4; nt++)
#pragma unroll
                for (int j = 0; j < 4; j++) sc[nt][j] = 0.f;
#pragma unroll
            for (int nt = 0; nt < 4; nt++) {
                const uint32_t kbase = sK + (uint32_t)((nt * 8 + (lane & 7)) * PITCH) * 2 + (lane >> 3) * 16;
#pragma unroll
                for (int kp = 0; kp < 2; kp++) {
                    uint32_t kf[4];
                    ldsm_x4(kf, kbase + kp * 64);
                    mma_f16(sc[nt], qf[kp * 2],     &kf[0]);
                    mma_f16(sc[nt], qf[kp * 2 + 1], &kf[2]);
                }
            }

            float mx0 = -1e30f, mx1 = -1e30f;
#pragma unroll
            for (int nt = 0; nt < 4; nt++) {
                const int c0 = kt + nt * 8 + tig * 2, c1 = c0 + 1;
                float s2;
                s2 = sc[nt][0] * 0.125f;
                sc[nt][0] = (c0 >= row0 - WIN && c0 <= row0 + WIN && c0 <= khi) ? s2 : -1e30f;
                s2 = sc[nt][1] * 0.125f;
                sc[nt][1] = (c1 >= row0 - WIN && c1 <= row0 + WIN && c1 <= khi) ? s2 : -1e30f;
                s2 = sc[nt][2] * 0.125f;
                sc[nt][2] = (c0 >= row1 - WIN && c0 <= row1 + WIN && c0 <= khi) ? s2 : -1e30f;
                s2 = sc[nt][3] * 0.125f;
                sc[nt][3] = (c1 >= row1 - WIN && c1 <= row1 + WIN && c1 <= khi) ? s2 : -1e30f;
                mx0 = fmaxf(mx0, fmaxf(sc[nt][0], sc[nt][1]));
                mx1 = fmaxf(mx1, fmaxf(sc[nt][2], sc[nt][3]));
            }
            mx0 = fmaxf(mx0, __shfl_xor_sync(0xFFFFFFFFu, mx0, 1));
            mx0 = fmaxf(mx0, __shfl_xor_sync(0xFFFFFFFFu, mx0, 2));
            mx1 = fmaxf(mx1, __shfl_xor_sync(0xFFFFFFFFu, mx1, 1));
            mx1 = fmaxf(mx1, __shfl_xor_sync(0xFFFFFFFFu, mx1, 2));

            const float nm0 = fmaxf(m0, mx0), nm1 = fmaxf(m1, mx1);
            const float e0 = __expf(m0 - nm0), e1 = __expf(m1 - nm1);
            l0 *= e0; l1 *= e1;
#pragma unroll
            for (int ng = 0; ng < 8; ng++) {
                o[ng][0] *= e0; o[ng][1] *= e0;
                o[ng][2] *= e1; o[ng][3] *= e1;
            }
            m0 = nm0; m1 = nm1;

            uint32_t pf[2][4];
#pragma unroll
            for (int nt = 0; nt < 4; nt++) {
                float p0 = __expf(sc[nt][0] - nm0), p1 = __expf(sc[nt][1] - nm0);
                float p2 = __expf(sc[nt][2] - nm1), p3 = __expf(sc[nt][3] - nm1);
                l0 += p0 + p1; l1 += p2 + p3;
                __half2 h01 = __floats2half2_rn(p0, p1);
                __half2 h23 = __floats2half2_rn(p2, p3);
                pf[nt >> 1][(nt & 1) * 2 + 0] = *(uint32_t*)&h01;
                pf[nt >> 1][(nt & 1) * 2 + 1] = *(uint32_t*)&h23;
            }

#pragma unroll
            for (int np = 0; np < 4; np++) {
#pragma unroll
                for (int kc = 0; kc < 2; kc++) {
                    uint32_t vf[4];
                    ldsm_x4_t(vf, sV + (uint32_t)((kc * 16 + (lane & 15)) * PITCH) * 2 +
                                  (np * 2 + (lane >> 4)) * 16);
                    mma_f16(o[np * 2],     pf[kc], &vf[0]);
                    mma_f16(o[np * 2 + 1], pf[kc], &vf[2]);
                }
            }
        }
    }

    l0 += __shfl_xor_sync(0xFFFFFFFFu, l0, 1);
    l0 += __shfl_xor_sync(0xFFFFFFFFu, l0, 2);
    l1 += __shfl_xor_sync(0xFFFFFFFFu, l1, 1);
    l1 += __shfl_xor_sync(0xFFFFFFFFu, l1, 2);
    const float inv0 = 1.f / l0, inv1 = 1.f / l1;
    __half* o0p = outh + (size_t)(b * SS + row0) * DD + h * HD + tig * 2;
    __half* o1p = outh + (size_t)(b * SS + row1) * DD + h * HD + tig * 2;
#pragma unroll
    for (int ng = 0; ng < 8; ng++) {
        __half2 a = __floats2half2_rn(o[ng][0] * inv0, o[ng][1] * inv0);
        __half2 c = __floats2half2_rn(o[ng][2] * inv1, o[ng][3] * inv1);
        *(__half2*)(o0p + ng * 8) = a;
        *(__half2*)(o1p + ng * 8) = c;
    }
}

// ---------------- fused residual + LayerNorm --------------------------------
template<bool AFP16, bool WF32OUT>
__global__ __launch_bounds__(256)
void ln_kernel(const float* __restrict__ Af, const __half* __restrict__ Ah,
               const __half* __restrict__ Rh,
               const float* __restrict__ g, const float* __restrict__ be,
               float* __restrict__ out, __half* __restrict__ oh)
{
    const int row = blockIdx.x;
    const int t = threadIdx.x;
    const size_t base = (size_t)row * DD;

    float4 av;
    if (AFP16) {
        __half2 a01 = *(const __half2*)(Ah + base + t * 4);
        __half2 a23 = *(const __half2*)(Ah + base + t * 4 + 2);
        float2 lo = __half22float2(a01);
        float2 hi = __half22float2(a23);
        av = make_float4(lo.x, lo.y, hi.x, hi.y);
    } else {
        av = *(const float4*)(Af + base + t * 4);
    }
    __half2 r01 = *(const __half2*)(Rh + base + t * 4);
    __half2 r23 = *(const __half2*)(Rh + base + t * 4 + 2);
    float2 rlo = __half22float2(r01);
    float2 rhi = __half22float2(r23);
    float4 v = make_float4(av.x + rlo.x, av.y + rlo.y, av.z + rhi.x, av.w + rhi.y);

    float s = v.x + v.y + v.z + v.w;
    float q = v.x * v.x + v.y * v.y + v.z * v.z + v.w * v.w;
#pragma unroll
    for (int off = 16; off > 0; off >>= 1) {
        s += __shfl_xor_sync(0xFFFFFFFFu, s, off);
        q += __shfl_xor_sync(0xFFFFFFFFu, q, off);
    }
    __shared__ float ss[8], sq[8];
    __shared__ float mu_s, inv_s;
    if ((t & 31) == 0) { ss[t >> 5] = s; sq[t >> 5] = q; }
    __syncthreads();
    if (t == 0) {
        float S = 0.f, Q = 0.f;
#pragma unroll
        for (int i = 0; i < 8; i++) { S += ss[i]; Q += sq[i]; }
        float mu = S * (1.f / DD);
        float var = Q * (1.f / DD) - mu * mu;
        mu_s = mu;
        inv_s = rsqrtf(var + 1e-5f);
    }
    __syncthreads();
    const float mu = mu_s, inv = inv_s;

    float4 gv = *(const float4*)(g + t * 4);
    float4 bv = *(const float4*)(be + t * 4);
    float4 o;
    o.x = (v.x - mu) * inv * gv.x + bv.x;
    o.y = (v.y - mu) * inv * gv.y + bv.y;
    o.z = (v.z - mu) * inv * gv.z + bv.z;
    o.w = (v.w - mu) * inv * gv.w + bv.w;

    if (WF32OUT) {
        *(float4*)(out + base + t * 4) = o;
    } else {
        __half2 h0, h1;
        h0.x = __float2half_rn(o.x); h0.y = __float2half_rn(o.y);
        h1.x = __float2half_rn(o.z); h1.y = __float2half_rn(o.w);
        *(__half2*)(oh + base + t * 4)     = h0;
        *(__half2*)(oh + base + t * 4 + 2) = h1;
    }
}

// ---------------- host ----------------
extern "C" void kernel_launch(void* const* d_in, const int* in_sizes, int n_in,
                              void* d_out, int out_size)
{
    (void)in_sizes; (void)n_in; (void)out_size;
    const float* x     = (const float*)d_in[0];
    const float* in_w  = (const float*)d_in[1];
    const float* in_b  = (const float*)d_in[2];
    const float* out_w = (const float*)d_in[3];
    const float* out_b = (const float*)d_in[4];
    const float* ln1g  = (const float*)d_in[5];
    const float* ln1b  = (const float*)d_in[6];
    const float* w1    = (const float*)d_in[7];
    const float* b1    = (const float*)d_in[8];
    const float* w2    = (const float*)d_in[9];
    const float* b2    = (const float*)d_in[10];
    const float* ln2g  = (const float*)d_in[11];
    const float* ln2b  = (const float*)d_in[12];
    float* out = (float*)d_out;

    __half *tmph, *qkvh, *xh, *ath, *x2h, *ffh, *iwh, *owh, *w1h, *w2h;
    cudaGetSymbolAddress((void**)&tmph, g_tmph);
    cudaGetSymbolAddress((void**)&qkvh, g_qkvh);
    cudaGetSymbolAddress((void**)&xh,   g_x_h);
    cudaGetSymbolAddress((void**)&ath,  g_at_h);
    cudaGetSymbolAddress((void**)&x2h,  g_x2_h);
    cudaGetSymbolAddress((void**)&ffh,  g_ff_h);
    cudaGetSymbolAddress((void**)&iwh,  g_iw_h);
    cudaGetSymbolAddress((void**)&owh,  g_ow_h);
    cudaGetSymbolAddress((void**)&w1h,  g_w1_h);
    cudaGetSymbolAddress((void**)&w2h,  g_w2_h);

    cudaFuncSetAttribute(gemm_f16<false>,
                         cudaFuncAttributeMaxDynamicSharedMemorySize, GEMM_SMEM);
    cudaFuncSetAttribute(gemm_f16<true>,
                         cudaFuncAttributeMaxDynamicSharedMemorySize, GEMM_SMEM);
    cudaFuncSetAttribute(attn_mma,
                         cudaFuncAttributeMaxDynamicSharedMemorySize, ATTN_SMEM);

    cvt_all<<<(N4_TOT + 1023) / 1024, 512>>>(x, xh, in_w, iwh, out_w, owh, w1, w1h, w2, w2h);

    // 1. QKV projection -> fp16 qkv
    gemm_f16<false><<<dim3(3 * DD / 128, MTOT / 128), 256, GEMM_SMEM>>>(
        xh, iwh, in_b, qkvh, MTOT, 3 * DD, DD);
    // 2. MMA attention -> fp16 (64-key stages, 2-stage pipe, 2 CTAs/SM)
    attn_mma<<<dim3(SS / 128, HH, BB), 256, ATTN_SMEM>>>(qkvh, ath);
    // 3. out_proj -> fp16 tmp
    gemm_f16<false><<<dim3(DD / 128, MTOT / 128), 256, GEMM_SMEM>>>(
        ath, owh, out_b, tmph, MTOT, DD, DD);
    // 4. ln1 (x fp32 + tmp fp16) -> fp16 x2h only
    ln_kernel<false, false><<<MTOT, 256>>>(x, nullptr, tmph, ln1g, ln1b, nullptr, x2h);
    // 5. ffn1 (relu) -> fp16
    gemm_f16<true><<<dim3(DFF / 128, MTOT / 128), 256, GEMM_SMEM>>>(
        x2h, w1h, b1, ffh, MTOT, DFF, DD);
    // 6. ffn2 -> fp16 tmp
    gemm_f16<false><<<dim3(DD / 128, MTOT / 128), 256, GEMM_SMEM>>>(
        ffh, w2h, b2, tmph, MTOT, DD, DFF);
    // 7. ln2 (x2h fp16 + tmp fp16) -> final fp32 out
    ln_kernel<true, true><<<MTOT, 256>>>(nullptr, x2h, tmph, ln2g, ln2b, out, nullptr);
}